// round 12
// baseline (speedup 1.0000x reference)
#include <cuda_runtime.h>
#include <cuda_fp16.h>
#include <math.h>
#include <stdint.h>

#define B_   2
#define N_   4
#define T_   1024
#define D_   512
#define E_   16
#define KX   15          // computed experts (1..15)
#define DFFN 828
#define ND   2048        // N_*D_
#define MTOK 2048        // B_*T_
#define KSPLIT 32        // split-K factor for MHC projection

// ---------------- scratch (device globals; no allocation) ----------------
__device__ float g_xn[MTOK * ND];
__device__ int   g_cnt[KX];
__device__ int   g_idx[KX][MTOK];
__device__ int   g_pos[KX][MTOK];
__device__ float g_rs[(long)KX * 16 * 24 * KSPLIT * 128];
__device__ float g_Hpre[KX][MTOK][4];
__device__ float g_Hpost[KX][MTOK][4];
__device__ float g_Hres[KX][MTOK][16];
__device__ float g_gate[KX][MTOK];
__device__ float g_h[KX][MTOK][D_];
__device__ float g_s1[KX][MTOK][D_];
__device__ float g_gsig[KX][MTOK][D_];
__device__ float g_t1[KX][MTOK][DFFN];
__device__ float g_t2[KX][MTOK][DFFN];
__device__ float g_oute[KX][MTOK][D_];

__device__ __forceinline__ float sigmoidf_(float x) { return 1.f / (1.f + expf(-x)); }

__device__ __forceinline__ float block_reduce_sum(float v, float* sbuf) {
    int tid = threadIdx.x;
    #pragma unroll
    for (int o = 16; o > 0; o >>= 1) v += __shfl_down_sync(0xffffffffu, v, o);
    if ((tid & 31) == 0) sbuf[tid >> 5] = v;
    __syncthreads();
    int nw = blockDim.x >> 5;
    float r = (tid < nw) ? sbuf[tid] : 0.f;
    if (tid < 32) {
        #pragma unroll
        for (int o = 16; o > 0; o >>= 1) r += __shfl_down_sync(0xffffffffu, r, o);
        if (tid == 0) sbuf[0] = r;
    }
    __syncthreads();
    return sbuf[0];
}

// ---------------- K-1: zero per-expert counters ---------------------------
__global__ void zero_cnt_kernel() {
    if (threadIdx.x < KX) g_cnt[threadIdx.x] = 0;
}

// ---------------- K0: routing + compaction lists --------------------------
__global__ void routing_kernel(const float* __restrict__ stream,
                               const float* __restrict__ router_w,
                               float* __restrict__ out)
{
    int t = blockIdx.x;
    int b = t >> 10, tt = t & 1023;
    int tid = threadIdx.x;           // 128
    __shared__ float sred[E_][128];

    float acc[E_];
    #pragma unroll
    for (int e = 0; e < E_; e++) acc[e] = 0.f;

    for (int d = tid; d < D_; d += 128) {
        float ri = 0.f;
        #pragma unroll
        for (int n = 0; n < N_; n++)
            ri += stream[(((long)(b * N_ + n)) * T_ + tt) * D_ + d];
        ri *= 0.25f;
        #pragma unroll
        for (int e = 0; e < E_; e++) acc[e] += ri * router_w[e * D_ + d];
    }
    #pragma unroll
    for (int e = 0; e < E_; e++) sred[e][tid] = acc[e];
    __syncthreads();
    for (int s = 64; s > 0; s >>= 1) {
        if (tid < s) {
            #pragma unroll
            for (int e = 0; e < E_; e++) sred[e][tid] += sred[e][tid + s];
        }
        __syncthreads();
    }

    if (tid == 0) {
        float probs[E_];
        float mx = -1e30f;
        for (int e = 0; e < E_; e++) mx = fmaxf(mx, sred[e][0]);
        float ssum = 0.f;
        for (int e = 0; e < E_; e++) { probs[e] = expf(sred[e][0] - mx); ssum += probs[e]; }
        float inv = 1.f / ssum;
        for (int e = 0; e < E_; e++) probs[e] *= inv;

        int order[E_];
        for (int e = 0; e < E_; e++) order[e] = e;
        for (int i = 1; i < E_; i++) {
            int oi = order[i]; float p = probs[oi]; int j = i - 1;
            while (j >= 0 && probs[order[j]] < p) { order[j + 1] = order[j]; j--; }
            order[j + 1] = oi;
        }
        float gate[E_];
        for (int e = 0; e < E_; e++) gate[e] = 0.f;
        float cum = 0.f;
        for (int i = 0; i < E_; i++) {
            float p = probs[order[i]];
            bool m = (i == 0) || ((cum < 0.8f) && (i < 4));
            if (m) gate[order[i]] = p;
            cum += p;
        }
        float lp = 0.f;
        for (int e = 0; e < E_; e++)
            if (gate[e] > 0.f) lp += fmaxf(logf(probs[e]), -10.f);

        float* out_gate = out + (long)B_ * N_ * T_ * D_;
        float* out_lp   = out_gate + (long)B_ * T_ * E_;
        for (int e = 0; e < E_; e++) out_gate[(long)t * E_ + e] = gate[e];
        out_lp[t] = lp;
        for (int k = 0; k < KX; k++) {
            float gk = gate[k + 1];
            g_gate[k][t] = gk;
            if (gk > 0.f) {
                int p = atomicAdd(&g_cnt[k], 1);
                g_idx[k][p] = t;
                g_pos[k][t] = p;
            } else {
                g_pos[k][t] = -1;
            }
        }
    }
}

// ---------------- K1: xn = RMSNorm over nd of transposed stream ----------
__global__ void xn_kernel(const float* __restrict__ stream)
{
    int t = blockIdx.x;
    int b = t >> 10, tt = t & 1023;
    int tid = threadIdx.x;           // 256
    __shared__ float sbuf[32];
    float v[8]; float ss = 0.f;
    #pragma unroll
    for (int i = 0; i < 8; i++) {
        int j = tid + i * 256;
        int n = j >> 9, d = j & 511;
        float x = stream[(((long)(b * N_ + n)) * T_ + tt) * D_ + d];
        v[i] = x; ss += x * x;
    }
    float tot = block_reduce_sum(ss, sbuf);
    float rms = rsqrtf(tot * (1.f / ND) + 1e-8f);
    #pragma unroll
    for (int i = 0; i < 8; i++)
        g_xn[(long)t * ND + tid + i * 256] = v[i] * rms;
}

// ---------------- K2a: MHC projection partials (split-K) -----------------
__global__ __launch_bounds__(256) void mhc_part(
    const float* __restrict__ norm_w,
    const float* __restrict__ phi_pre, const float* __restrict__ phi_post,
    const float* __restrict__ phi_res)
{
    int tile = blockIdx.x;
    int k = blockIdx.y; int e = k + 1;
    int ks = blockIdx.z;
    int t0 = tile * 128;
    int cnt = g_cnt[k];
    if (t0 >= cnt) return;
    int tid = threadIdx.x;

    __shared__ int   tok[128];
    __shared__ float xs[32][129];
    __shared__ float ws[32][25];

    if (tid < 128) {
        int s = t0 + tid;
        tok[tid] = (s < cnt) ? g_idx[k][s] : g_idx[k][0];
    }
    __syncthreads();

    int r = tid & 63;
    int q = tid >> 6;

    float acc[2][6];
    #pragma unroll
    for (int a = 0; a < 2; a++)
        #pragma unroll
        for (int m = 0; m < 6; m++) acc[a][m] = 0.f;

    const int kbeg = ks * (ND / KSPLIT);
    const int kend = kbeg + (ND / KSPLIT);
    for (int kb = kbeg; kb < kend; kb += 32) {
        #pragma unroll
        for (int i = 0; i < 16; i++) {
            int lin = tid + i * 256;
            int trow = lin >> 5, tcol = lin & 31;
            xs[tcol][trow] = g_xn[(long)tok[trow] * ND + kb + tcol];
        }
        #pragma unroll
        for (int i = 0; i < 3; i++) {
            int lin = tid + i * 256;
            int jrow = lin >> 5, kcol = lin & 31;
            int gk = kb + kcol;
            const float* wr;
            if (jrow < 4)      wr = phi_pre  + (long)(e * 4  + jrow)       * ND;
            else if (jrow < 8) wr = phi_post + (long)(e * 4  + (jrow - 4)) * ND;
            else               wr = phi_res  + (long)(e * 16 + (jrow - 8)) * ND;
            ws[kcol][jrow] = wr[gk] * norm_w[(long)e * ND + gk];
        }
        __syncthreads();
        #pragma unroll
        for (int kk = 0; kk < 32; kk++) {
            float x0 = xs[kk][r], x1 = xs[kk][r + 64];
            #pragma unroll
            for (int m = 0; m < 6; m++) {
                float w = ws[kk][q + m * 4];
                acc[0][m] += x0 * w;
                acc[1][m] += x1 * w;
            }
        }
        __syncthreads();
    }

    long base = ((long)(k * 16 + tile)) * 24;
    #pragma unroll
    for (int m = 0; m < 6; m++) {
        int j = q + m * 4;
        long o = ((base + j) * KSPLIT + ks) * 128;
        g_rs[o + r]      = acc[0][m];
        g_rs[o + r + 64] = acc[1][m];
    }
}

// ---------------- K2b: sum partials + sigmoid/sinkhorn epilogue ----------
__global__ void mhc_epi(
    const float* __restrict__ b_pre, const float* __restrict__ b_post,
    const float* __restrict__ b_res,
    const float* __restrict__ alpha_pre, const float* __restrict__ alpha_post,
    const float* __restrict__ alpha_res)
{
    int tile = blockIdx.x;
    int k = blockIdx.y; int e = k + 1;
    int cnt = g_cnt[k];
    int slot = tile * 128 + threadIdx.x;
    if (slot >= cnt) return;

    float rsv[24];
    long base = ((long)(k * 16 + tile)) * 24;
    #pragma unroll
    for (int j = 0; j < 24; j++) {
        long o = (base + j) * KSPLIT * 128 + threadIdx.x;
        float s = 0.f;
        #pragma unroll
        for (int ks = 0; ks < KSPLIT; ks++) s += g_rs[o + (long)ks * 128];
        rsv[j] = s;
    }

    float ap  = alpha_pre[e];
    float apo = alpha_post[e];
    float ar  = alpha_res[e];
    #pragma unroll
    for (int n = 0; n < 4; n++) {
        g_Hpre[k][slot][n]  = sigmoidf_(ap  * rsv[n]     + b_pre[e * 4 + n]);
        g_Hpost[k][slot][n] = 2.f * sigmoidf_(apo * rsv[4 + n] + b_post[e * 4 + n]);
    }
    float m[4][4];
    #pragma unroll
    for (int i = 0; i < 4; i++)
        #pragma unroll
        for (int j = 0; j < 4; j++)
            m[i][j] = expf(ar * rsv[8 + i * 4 + j] + b_res[e * 16 + i * 4 + j]);
    #pragma unroll
    for (int it = 0; it < 6; it++) {
        #pragma unroll
        for (int i = 0; i < 4; i++) {
            float s = m[i][0] + m[i][1] + m[i][2] + m[i][3];
            float iv = 1.f / s;
            m[i][0] *= iv; m[i][1] *= iv; m[i][2] *= iv; m[i][3] *= iv;
        }
        #pragma unroll
        for (int j = 0; j < 4; j++) {
            float s = m[0][j] + m[1][j] + m[2][j] + m[3][j];
            float iv = 1.f / s;
            m[0][j] *= iv; m[1][j] *= iv; m[2][j] *= iv; m[3][j] *= iv;
        }
    }
    #pragma unroll
    for (int i = 0; i < 4; i++)
        #pragma unroll
        for (int j = 0; j < 4; j++)
            g_Hres[k][slot][i * 4 + j] = m[i][j];
}

// ---------------- K3: h = RMSNorm(H_pre @ stream) * swiglu_norm_w --------
__global__ void he_kernel(const float* __restrict__ stream,
                          const float* __restrict__ snw)
{
    int k = blockIdx.x;
    int slot = blockIdx.y;
    if (slot >= g_cnt[k]) return;
    int t = g_idx[k][slot];
    int b = t >> 10, tt = t & 1023;
    int tid = threadIdx.x;
    __shared__ float sbuf[32];

    float hp[4];
    #pragma unroll
    for (int n = 0; n < 4; n++) hp[n] = g_Hpre[k][slot][n];

    float v[4]; float ss = 0.f;
    #pragma unroll
    for (int i = 0; i < 4; i++) {
        int d = tid + i * 128;
        float s = 0.f;
        #pragma unroll
        for (int n = 0; n < 4; n++)
            s += hp[n] * stream[(((long)(b * N_ + n)) * T_ + tt) * D_ + d];
        v[i] = s; ss += s * s;
    }
    float tot = block_reduce_sum(ss, sbuf);
    float rms = rsqrtf(tot * (1.f / D_) + 1e-8f);
    int e = k + 1;
    #pragma unroll
    for (int i = 0; i < 4; i++) {
        int d = tid + i * 128;
        g_h[k][slot][d] = v[i] * rms * snw[e * D_ + d];
    }
}

// ---------------- 3x split-FP16 mma.sync GEMM, 64x128 tile ---------------
// C[M,N] = epi(A[M,Kd] @ W[N,Kd]^T), per expert z.
#define EPI_SILU    0
#define EPI_SIGMOID 1
#define EPI_MUL     2

__device__ __forceinline__ void split_h2(float2 v, uint32_t& hi, uint32_t& lo) {
    __half2 h = __float22half2_rn(v);
    float2 back = __half22float2(h);
    __half2 l = __float22half2_rn(make_float2(v.x - back.x, v.y - back.y));
    hi = *(uint32_t*)&h;
    lo = *(uint32_t*)&l;
}

__device__ __forceinline__ void mma_f16(float* c, const uint32_t* a, const uint32_t* b) {
    asm volatile(
        "mma.sync.aligned.m16n8k16.row.col.f32.f16.f16.f32 "
        "{%0,%1,%2,%3}, {%4,%5,%6,%7}, {%8,%9}, {%0,%1,%2,%3};"
        : "+f"(c[0]), "+f"(c[1]), "+f"(c[2]), "+f"(c[3])
        : "r"(a[0]), "r"(a[1]), "r"(a[2]), "r"(a[3]), "r"(b[0]), "r"(b[1]));
}

__device__ __forceinline__ void cp_async16(uint32_t dst, const void* src, int src_size) {
    asm volatile("cp.async.cg.shared.global [%0], [%1], 16, %2;"
                 :: "r"(dst), "l"(src), "r"(src_size) : "memory");
}
#define CP_COMMIT() asm volatile("cp.async.commit_group;" ::: "memory")
#define CP_WAIT(n)  asm volatile("cp.async.wait_group %0;" :: "n"(n) : "memory")

// smem rows of 16 k-floats padded to 24 (conflict-free LDS.64)
#define GSTRIDE 24
#define ABUF (64 * GSTRIDE)           // 1536 floats
#define BBUF (128 * GSTRIDE)          // 3072 floats
// layout: A0 | A1 | B0 | B1
#define GT_SMEM ((2 * ABUF + 2 * BBUF) * 4)   // 36 KB

// A tile: 64 rows x 4 chunks = 256 tasks (1/thread)
__device__ __forceinline__ void issue_A(
    uint32_t addr, const float* A, int rowBase, int Kd, int kb, int tid)
{
    int row = tid >> 2, k4 = tid & 3;
    int kg  = kb + k4 * 4;
    int ok  = (kg < Kd) ? 16 : 0;
    cp_async16(addr + (uint32_t)(row * (GSTRIDE * 4) + k4 * 16),
               A + (long)(rowBase + row) * Kd + kg, ok);
}
// B tile: 128 rows x 4 chunks = 512 tasks (2/thread)
__device__ __forceinline__ void issue_B(
    uint32_t addr, const float* W, int colBase, int N, int Kd, int kb, int tid)
{
    #pragma unroll
    for (int i = 0; i < 2; i++) {
        int c = tid + i * 256;
        int row = c >> 2, k4 = c & 3;
        int kg  = kb + k4 * 4;
        int wr  = colBase + row;
        int wc  = (wr < N) ? wr : (N - 1);
        int ok  = (wr < N && kg < Kd) ? 16 : 0;
        cp_async16(addr + (uint32_t)(row * (GSTRIDE * 4) + k4 * 16),
                   W + (long)wc * Kd + kg, ok);
    }
}

__global__ __launch_bounds__(256) void sgemm_tc(
    const float* __restrict__ Abase, long sA,
    const float* __restrict__ Wbase, long sW,
    float* __restrict__ Cbase, long sC,
    const float* __restrict__ Xbase, long sX,
    int N, int Kd, int epi)
{
    int z = blockIdx.z;
    int Me = g_cnt[z];
    int rowBase = blockIdx.y * 64;
    if (rowBase >= Me) return;
    int colBase = blockIdx.x * 128;

    extern __shared__ __align__(16) float sdyn[];

    const float* A = Abase + (long)z * sA;
    const float* W = Wbase + (long)z * sW;
    float*       C = Cbase + (long)z * sC;
    const float* X = Xbase ? (Xbase + (long)z * sX) : nullptr;

    int tid  = threadIdx.x;
    int wid  = tid >> 5, lane = tid & 31;
    int gid  = lane >> 2, tig = lane & 3;
    int warpM = wid & 1, warpN = wid >> 1;     // 2 x 4 warp grid
    int m0 = warpM * 32;                       // warp tile 32 x 32
    int n0 = warpN * 32;

    uint32_t sbase;
    asm("{ .reg .u64 t; cvta.to.shared.u64 t, %1; cvt.u32.u64 %0, t; }"
        : "=r"(sbase) : "l"((const void*)sdyn));
    uint32_t aA = sbase;
    uint32_t bA = sbase + 2 * ABUF * 4;

    float acc[2][4][4];
    #pragma unroll
    for (int i = 0; i < 2; i++)
        #pragma unroll
        for (int j = 0; j < 4; j++)
            #pragma unroll
            for (int q = 0; q < 4; q++) acc[i][j][q] = 0.f;

    int nstages = (Kd + 15) >> 4;
    int kk = 2 * tig;

    issue_A(aA, A, rowBase, Kd, 0, tid);
    issue_B(bA, W, colBase, N, Kd, 0, tid);
    CP_COMMIT();

    for (int st = 0; st < nstages; st++) {
        if (st + 1 < nstages) {
            int buf = (st + 1) & 1;
            issue_A(aA + buf * ABUF * 4, A, rowBase, Kd, (st + 1) << 4, tid);
            issue_B(bA + buf * BBUF * 4, W, colBase, N, Kd, (st + 1) << 4, tid);
            CP_COMMIT();
            CP_WAIT(1);
        } else {
            CP_WAIT(0);
        }
        __syncthreads();

        const float* As = sdyn + (st & 1) * ABUF;
        const float* Bs = sdyn + 2 * ABUF + (st & 1) * BBUF;

        uint32_t aH[2][4], aL[2][4];
        #pragma unroll
        for (int mf = 0; mf < 2; mf++) {
            int mr0 = (m0 + mf * 16 + gid) * GSTRIDE;
            int mr1 = mr0 + 8 * GSTRIDE;
            split_h2(*(const float2*)(As + mr0 + kk),     aH[mf][0], aL[mf][0]);
            split_h2(*(const float2*)(As + mr1 + kk),     aH[mf][1], aL[mf][1]);
            split_h2(*(const float2*)(As + mr0 + kk + 8), aH[mf][2], aL[mf][2]);
            split_h2(*(const float2*)(As + mr1 + kk + 8), aH[mf][3], aL[mf][3]);
        }
        #pragma unroll
        for (int nf = 0; nf < 4; nf++) {
            int nr = (n0 + nf * 8 + gid) * GSTRIDE;
            uint32_t bh[2], bl[2];
            split_h2(*(const float2*)(Bs + nr + kk),     bh[0], bl[0]);
            split_h2(*(const float2*)(Bs + nr + kk + 8), bh[1], bl[1]);
            mma_f16(acc[0][nf], aH[0], bh);
            mma_f16(acc[1][nf], aH[1], bh);
            mma_f16(acc[0][nf], aL[0], bh);
            mma_f16(acc[1][nf], aL[1], bh);
            mma_f16(acc[0][nf], aH[0], bl);
            mma_f16(acc[1][nf], aH[1], bl);
        }
        __syncthreads();
    }

    // ---- epilogue ----
    #pragma unroll
    for (int mf = 0; mf < 2; mf++) {
        #pragma unroll
        for (int nf = 0; nf < 4; nf++) {
            #pragma unroll
            for (int q = 0; q < 4; q++) {
                int rr = rowBase + m0 + mf * 16 + gid + (q >> 1) * 8;
                int cc = colBase + n0 + nf * 8 + 2 * tig + (q & 1);
                if (rr < Me && cc < N) {
                    float v = acc[mf][nf][q];
                    long idx = (long)rr * N + cc;
                    if (epi == EPI_SILU)         v = v * (1.f / (1.f + expf(-v)));
                    else if (epi == EPI_SIGMOID) v = 1.f / (1.f + expf(-v));
                    else                         v = v * X[idx];
                    C[idx] = v;
                }
            }
        }
    }
}

// ---------------- K5: combine (res + post, gated sum over experts) -------
__global__ void combine_kernel(const float* __restrict__ stream,
                               float* __restrict__ out)
{
    int t = blockIdx.x;
    int b = t >> 10, tt = t & 1023;
    int tid = threadIdx.x;      // 256
    __shared__ float cres[16];
    __shared__ float pc[KX][4];
    __shared__ float gsh[KX];
    __shared__ int   posh[KX];

    if (tid < KX) {
        gsh[tid]  = g_gate[tid][t];
        posh[tid] = g_pos[tid][t];
    }
    __syncthreads();
    if (tid < 16) {
        float s = 0.f;
        for (int kk = 0; kk < KX; kk++) {
            int p = posh[kk];
            if (p >= 0) s += gsh[kk] * g_Hres[kk][p][tid];
        }
        cres[tid] = s;
    } else if (tid >= 32 && tid < 32 + KX * 4) {
        int idx = tid - 32; int kk = idx >> 2, i = idx & 3;
        int p = posh[kk];
        pc[kk][i] = (p >= 0) ? gsh[kk] * g_Hpost[kk][p][i] : 0.f;
    }
    __syncthreads();

    for (int d = tid; d < D_; d += 256) {
        float sj[4];
        #pragma unroll
        for (int j = 0; j < 4; j++)
            sj[j] = stream[(((long)(b * N_ + j)) * T_ + tt) * D_ + d];
        float r[4];
        #pragma unroll
        for (int i = 0; i < 4; i++)
            r[i] = cres[i * 4 + 0] * sj[0] + cres[i * 4 + 1] * sj[1]
                 + cres[i * 4 + 2] * sj[2] + cres[i * 4 + 3] * sj[3];
        for (int kk = 0; kk < KX; kk++) {
            int p = posh[kk];
            if (p >= 0) {
                float oe = g_oute[kk][p][d];
                #pragma unroll
                for (int i = 0; i < 4; i++) r[i] += pc[kk][i] * oe;
            }
        }
        #pragma unroll
        for (int i = 0; i < 4; i++)
            out[(((long)(b * N_ + i)) * T_ + tt) * D_ + d] = r[i];
    }
}

// ---------------- launch ----------------
extern "C" void kernel_launch(void* const* d_in, const int* in_sizes, int n_in,
                              void* d_out, int out_size)
{
    const float* stream    = (const float*)d_in[0];
    const float* norm_w    = (const float*)d_in[1];
    const float* phi_pre   = (const float*)d_in[2];
    const float* phi_post  = (const float*)d_in[3];
    const float* phi_res   = (const float*)d_in[4];
    const float* b_pre     = (const float*)d_in[5];
    const float* b_post    = (const float*)d_in[6];
    const float* b_res     = (const float*)d_in[7];
    const float* alpha_pre = (const float*)d_in[8];
    const float* alpha_post= (const float*)d_in[9];
    const float* alpha_res = (const float*)d_in[10];
    const float* snw       = (const float*)d_in[11];
    const float* wd        = (const float*)d_in[12];
    const float* wu        = (const float*)d_in[13];
    const float* wg        = (const float*)d_in[14];
    const float* wup       = (const float*)d_in[15];
    const float* wdn       = (const float*)d_in[16];
    const float* rw        = (const float*)d_in[17];
    float* out = (float*)d_out;

    float *p_h, *p_s1, *p_g, *p_t1, *p_t2, *p_oe;
    cudaGetSymbolAddress((void**)&p_h,  g_h);
    cudaGetSymbolAddress((void**)&p_s1, g_s1);
    cudaGetSymbolAddress((void**)&p_g,  g_gsig);
    cudaGetSymbolAddress((void**)&p_t1, g_t1);
    cudaGetSymbolAddress((void**)&p_t2, g_t2);
    cudaGetSymbolAddress((void**)&p_oe, g_oute);

    cudaFuncSetAttribute(sgemm_tc, cudaFuncAttributeMaxDynamicSharedMemorySize, GT_SMEM);

    zero_cnt_kernel<<<1, 32>>>();
    routing_kernel<<<MTOK, 128>>>(stream, rw, out);
    xn_kernel<<<MTOK, 256>>>(stream);
    mhc_part<<<dim3(16, KX, KSPLIT), 256>>>(norm_w, phi_pre, phi_post, phi_res);
    mhc_epi<<<dim3(16, KX), 128>>>(b_pre, b_post, b_res,
                                   alpha_pre, alpha_post, alpha_res);
    he_kernel<<<dim3(KX, MTOK), 128>>>(stream, snw);

    long sHD = (long)MTOK * D_;
    long sHF = (long)MTOK * DFFN;

    // row tiles of 64 cover up to MTOK tokens; blocks past cnt early-exit
    // s1 = silu(h @ wd^T)
    sgemm_tc<<<dim3(4, 32, KX), 256, GT_SMEM>>>(p_h, sHD, wd + (long)D_ * D_,
                                                (long)D_ * D_, p_s1, sHD,
                                                nullptr, 0, D_, D_, EPI_SILU);
    // g = sigmoid(s1 @ wu^T)
    sgemm_tc<<<dim3(4, 32, KX), 256, GT_SMEM>>>(p_s1, sHD, wu + (long)D_ * D_,
                                                (long)D_ * D_, p_g, sHD,
                                                nullptr, 0, D_, D_, EPI_SIGMOID);
    // t1 = silu(h @ gate^T)
    sgemm_tc<<<dim3(7, 32, KX), 256, GT_SMEM>>>(p_h, sHD, wg + (long)DFFN * D_,
                                                (long)DFFN * D_, p_t1, sHF,
                                                nullptr, 0, DFFN, D_, EPI_SILU);
    // t2 = (h @ up^T) * t1
    sgemm_tc<<<dim3(7, 32, KX), 256, GT_SMEM>>>(p_h, sHD, wup + (long)DFFN * D_,
                                                (long)DFFN * D_, p_t2, sHF,
                                                p_t1, sHF, DFFN, D_, EPI_MUL);
    // out_e = (t2 @ down^T) * g
    sgemm_tc<<<dim3(4, 32, KX), 256, GT_SMEM>>>(p_t2, sHF, wdn + (long)D_ * DFFN,
                                                (long)D_ * DFFN, p_oe, sHD,
                                                p_g, sHD, D_, DFFN, EPI_MUL);

    combine_kernel<<<MTOK, 256>>>(stream, out);
}

// round 13
// speedup vs baseline: 1.4849x; 1.4849x over previous
#include <cuda_runtime.h>
#include <cuda_fp16.h>
#include <math.h>
#include <stdint.h>

#define B_   2
#define N_   4
#define T_   1024
#define D_   512
#define E_   16
#define KX   15          // computed experts (1..15)
#define DFFN 828
#define ND   2048        // N_*D_
#define MTOK 2048        // B_*T_
#define KSPLIT 32        // split-K factor for MHC projection

// ---------------- scratch (device globals; no allocation) ----------------
__device__ float g_xn[MTOK * ND];
__device__ int   g_cnt[KX];
__device__ int   g_idx[KX][MTOK];
__device__ int   g_pos[KX][MTOK];
__device__ float g_rs[(long)KX * 16 * 24 * KSPLIT * 128];
__device__ float g_Hpre[KX][MTOK][4];
__device__ float g_Hpost[KX][MTOK][4];
__device__ float g_Hres[KX][MTOK][16];
__device__ float g_gate[KX][MTOK];
__device__ float g_h[KX][MTOK][D_];
__device__ float g_s1[KX][MTOK][D_];
__device__ float g_gsig[KX][MTOK][D_];
__device__ float g_t1[KX][MTOK][DFFN];
__device__ float g_t2[KX][MTOK][DFFN];
__device__ float g_oute[KX][MTOK][D_];

__device__ __forceinline__ float sigmoidf_(float x) { return 1.f / (1.f + expf(-x)); }

__device__ __forceinline__ float block_reduce_sum(float v, float* sbuf) {
    int tid = threadIdx.x;
    #pragma unroll
    for (int o = 16; o > 0; o >>= 1) v += __shfl_down_sync(0xffffffffu, v, o);
    if ((tid & 31) == 0) sbuf[tid >> 5] = v;
    __syncthreads();
    int nw = blockDim.x >> 5;
    float r = (tid < nw) ? sbuf[tid] : 0.f;
    if (tid < 32) {
        #pragma unroll
        for (int o = 16; o > 0; o >>= 1) r += __shfl_down_sync(0xffffffffu, r, o);
        if (tid == 0) sbuf[0] = r;
    }
    __syncthreads();
    return sbuf[0];
}

// ---------------- K-1: zero per-expert counters ---------------------------
__global__ void zero_cnt_kernel() {
    if (threadIdx.x < KX) g_cnt[threadIdx.x] = 0;
}

// ---------------- K0: routing + compaction lists --------------------------
__global__ void routing_kernel(const float* __restrict__ stream,
                               const float* __restrict__ router_w,
                               float* __restrict__ out)
{
    int t = blockIdx.x;
    int b = t >> 10, tt = t & 1023;
    int tid = threadIdx.x;           // 128
    __shared__ float sred[E_][128];

    float acc[E_];
    #pragma unroll
    for (int e = 0; e < E_; e++) acc[e] = 0.f;

    for (int d = tid; d < D_; d += 128) {
        float ri = 0.f;
        #pragma unroll
        for (int n = 0; n < N_; n++)
            ri += stream[(((long)(b * N_ + n)) * T_ + tt) * D_ + d];
        ri *= 0.25f;
        #pragma unroll
        for (int e = 0; e < E_; e++) acc[e] += ri * router_w[e * D_ + d];
    }
    #pragma unroll
    for (int e = 0; e < E_; e++) sred[e][tid] = acc[e];
    __syncthreads();
    for (int s = 64; s > 0; s >>= 1) {
        if (tid < s) {
            #pragma unroll
            for (int e = 0; e < E_; e++) sred[e][tid] += sred[e][tid + s];
        }
        __syncthreads();
    }

    if (tid == 0) {
        float probs[E_];
        float mx = -1e30f;
        for (int e = 0; e < E_; e++) mx = fmaxf(mx, sred[e][0]);
        float ssum = 0.f;
        for (int e = 0; e < E_; e++) { probs[e] = expf(sred[e][0] - mx); ssum += probs[e]; }
        float inv = 1.f / ssum;
        for (int e = 0; e < E_; e++) probs[e] *= inv;

        int order[E_];
        for (int e = 0; e < E_; e++) order[e] = e;
        for (int i = 1; i < E_; i++) {
            int oi = order[i]; float p = probs[oi]; int j = i - 1;
            while (j >= 0 && probs[order[j]] < p) { order[j + 1] = order[j]; j--; }
            order[j + 1] = oi;
        }
        float gate[E_];
        for (int e = 0; e < E_; e++) gate[e] = 0.f;
        float cum = 0.f;
        for (int i = 0; i < E_; i++) {
            float p = probs[order[i]];
            bool m = (i == 0) || ((cum < 0.8f) && (i < 4));
            if (m) gate[order[i]] = p;
            cum += p;
        }
        float lp = 0.f;
        for (int e = 0; e < E_; e++)
            if (gate[e] > 0.f) lp += fmaxf(logf(probs[e]), -10.f);

        float* out_gate = out + (long)B_ * N_ * T_ * D_;
        float* out_lp   = out_gate + (long)B_ * T_ * E_;
        for (int e = 0; e < E_; e++) out_gate[(long)t * E_ + e] = gate[e];
        out_lp[t] = lp;
        for (int k = 0; k < KX; k++) {
            float gk = gate[k + 1];
            g_gate[k][t] = gk;
            if (gk > 0.f) {
                int p = atomicAdd(&g_cnt[k], 1);
                g_idx[k][p] = t;
                g_pos[k][t] = p;
            } else {
                g_pos[k][t] = -1;
            }
        }
    }
}

// ---------------- K1: xn = RMSNorm over nd of transposed stream ----------
__global__ void xn_kernel(const float* __restrict__ stream)
{
    int t = blockIdx.x;
    int b = t >> 10, tt = t & 1023;
    int tid = threadIdx.x;           // 256
    __shared__ float sbuf[32];
    float v[8]; float ss = 0.f;
    #pragma unroll
    for (int i = 0; i < 8; i++) {
        int j = tid + i * 256;
        int n = j >> 9, d = j & 511;
        float x = stream[(((long)(b * N_ + n)) * T_ + tt) * D_ + d];
        v[i] = x; ss += x * x;
    }
    float tot = block_reduce_sum(ss, sbuf);
    float rms = rsqrtf(tot * (1.f / ND) + 1e-8f);
    #pragma unroll
    for (int i = 0; i < 8; i++)
        g_xn[(long)t * ND + tid + i * 256] = v[i] * rms;
}

// ---------------- K2a: MHC projection partials (split-K) -----------------
__global__ __launch_bounds__(256) void mhc_part(
    const float* __restrict__ norm_w,
    const float* __restrict__ phi_pre, const float* __restrict__ phi_post,
    const float* __restrict__ phi_res)
{
    int tile = blockIdx.x;
    int k = blockIdx.y; int e = k + 1;
    int ks = blockIdx.z;
    int t0 = tile * 128;
    int cnt = g_cnt[k];
    if (t0 >= cnt) return;
    int tid = threadIdx.x;

    __shared__ int   tok[128];
    __shared__ float xs[32][129];
    __shared__ float ws[32][25];

    if (tid < 128) {
        int s = t0 + tid;
        tok[tid] = (s < cnt) ? g_idx[k][s] : g_idx[k][0];
    }
    __syncthreads();

    int r = tid & 63;
    int q = tid >> 6;

    float acc[2][6];
    #pragma unroll
    for (int a = 0; a < 2; a++)
        #pragma unroll
        for (int m = 0; m < 6; m++) acc[a][m] = 0.f;

    const int kbeg = ks * (ND / KSPLIT);
    const int kend = kbeg + (ND / KSPLIT);
    for (int kb = kbeg; kb < kend; kb += 32) {
        #pragma unroll
        for (int i = 0; i < 16; i++) {
            int lin = tid + i * 256;
            int trow = lin >> 5, tcol = lin & 31;
            xs[tcol][trow] = g_xn[(long)tok[trow] * ND + kb + tcol];
        }
        #pragma unroll
        for (int i = 0; i < 3; i++) {
            int lin = tid + i * 256;
            int jrow = lin >> 5, kcol = lin & 31;
            int gk = kb + kcol;
            const float* wr;
            if (jrow < 4)      wr = phi_pre  + (long)(e * 4  + jrow)       * ND;
            else if (jrow < 8) wr = phi_post + (long)(e * 4  + (jrow - 4)) * ND;
            else               wr = phi_res  + (long)(e * 16 + (jrow - 8)) * ND;
            ws[kcol][jrow] = wr[gk] * norm_w[(long)e * ND + gk];
        }
        __syncthreads();
        #pragma unroll
        for (int kk = 0; kk < 32; kk++) {
            float x0 = xs[kk][r], x1 = xs[kk][r + 64];
            #pragma unroll
            for (int m = 0; m < 6; m++) {
                float w = ws[kk][q + m * 4];
                acc[0][m] += x0 * w;
                acc[1][m] += x1 * w;
            }
        }
        __syncthreads();
    }

    long base = ((long)(k * 16 + tile)) * 24;
    #pragma unroll
    for (int m = 0; m < 6; m++) {
        int j = q + m * 4;
        long o = ((base + j) * KSPLIT + ks) * 128;
        g_rs[o + r]      = acc[0][m];
        g_rs[o + r + 64] = acc[1][m];
    }
}

// ---------------- K2b: sum partials + sigmoid/sinkhorn epilogue ----------
__global__ void mhc_epi(
    const float* __restrict__ b_pre, const float* __restrict__ b_post,
    const float* __restrict__ b_res,
    const float* __restrict__ alpha_pre, const float* __restrict__ alpha_post,
    const float* __restrict__ alpha_res)
{
    int tile = blockIdx.x;
    int k = blockIdx.y; int e = k + 1;
    int cnt = g_cnt[k];
    int slot = tile * 128 + threadIdx.x;
    if (slot >= cnt) return;

    float rsv[24];
    long base = ((long)(k * 16 + tile)) * 24;
    #pragma unroll
    for (int j = 0; j < 24; j++) {
        long o = (base + j) * KSPLIT * 128 + threadIdx.x;
        float s = 0.f;
        #pragma unroll
        for (int ks = 0; ks < KSPLIT; ks++) s += g_rs[o + (long)ks * 128];
        rsv[j] = s;
    }

    float ap  = alpha_pre[e];
    float apo = alpha_post[e];
    float ar  = alpha_res[e];
    #pragma unroll
    for (int n = 0; n < 4; n++) {
        g_Hpre[k][slot][n]  = sigmoidf_(ap  * rsv[n]     + b_pre[e * 4 + n]);
        g_Hpost[k][slot][n] = 2.f * sigmoidf_(apo * rsv[4 + n] + b_post[e * 4 + n]);
    }
    float m[4][4];
    #pragma unroll
    for (int i = 0; i < 4; i++)
        #pragma unroll
        for (int j = 0; j < 4; j++)
            m[i][j] = expf(ar * rsv[8 + i * 4 + j] + b_res[e * 16 + i * 4 + j]);
    #pragma unroll
    for (int it = 0; it < 6; it++) {
        #pragma unroll
        for (int i = 0; i < 4; i++) {
            float s = m[i][0] + m[i][1] + m[i][2] + m[i][3];
            float iv = 1.f / s;
            m[i][0] *= iv; m[i][1] *= iv; m[i][2] *= iv; m[i][3] *= iv;
        }
        #pragma unroll
        for (int j = 0; j < 4; j++) {
            float s = m[0][j] + m[1][j] + m[2][j] + m[3][j];
            float iv = 1.f / s;
            m[0][j] *= iv; m[1][j] *= iv; m[2][j] *= iv; m[3][j] *= iv;
        }
    }
    #pragma unroll
    for (int i = 0; i < 4; i++)
        #pragma unroll
        for (int j = 0; j < 4; j++)
            g_Hres[k][slot][i * 4 + j] = m[i][j];
}

// ---------------- K3: h = RMSNorm(H_pre @ stream) * swiglu_norm_w --------
__global__ void he_kernel(const float* __restrict__ stream,
                          const float* __restrict__ snw)
{
    int k = blockIdx.x;
    int slot = blockIdx.y;
    if (slot >= g_cnt[k]) return;
    int t = g_idx[k][slot];
    int b = t >> 10, tt = t & 1023;
    int tid = threadIdx.x;
    __shared__ float sbuf[32];

    float hp[4];
    #pragma unroll
    for (int n = 0; n < 4; n++) hp[n] = g_Hpre[k][slot][n];

    float v[4]; float ss = 0.f;
    #pragma unroll
    for (int i = 0; i < 4; i++) {
        int d = tid + i * 128;
        float s = 0.f;
        #pragma unroll
        for (int n = 0; n < 4; n++)
            s += hp[n] * stream[(((long)(b * N_ + n)) * T_ + tt) * D_ + d];
        v[i] = s; ss += s * s;
    }
    float tot = block_reduce_sum(ss, sbuf);
    float rms = rsqrtf(tot * (1.f / D_) + 1e-8f);
    int e = k + 1;
    #pragma unroll
    for (int i = 0; i < 4; i++) {
        int d = tid + i * 128;
        g_h[k][slot][d] = v[i] * rms * snw[e * D_ + d];
    }
}

// ---------------- 3x split-FP16 mma.sync GEMM, 3-stage cp.async ----------
// C[M,N] = epi(A[M,Kd] @ W[N,Kd]^T), per expert z, tile 128x128.
#define EPI_SILU    0
#define EPI_SIGMOID 1
#define EPI_MUL     2

__device__ __forceinline__ void split_h2(float2 v, uint32_t& hi, uint32_t& lo) {
    __half2 h = __float22half2_rn(v);
    float2 back = __half22float2(h);
    __half2 l = __float22half2_rn(make_float2(v.x - back.x, v.y - back.y));
    hi = *(uint32_t*)&h;
    lo = *(uint32_t*)&l;
}

__device__ __forceinline__ void mma_f16(float* c, const uint32_t* a, const uint32_t* b) {
    asm volatile(
        "mma.sync.aligned.m16n8k16.row.col.f32.f16.f16.f32 "
        "{%0,%1,%2,%3}, {%4,%5,%6,%7}, {%8,%9}, {%0,%1,%2,%3};"
        : "+f"(c[0]), "+f"(c[1]), "+f"(c[2]), "+f"(c[3])
        : "r"(a[0]), "r"(a[1]), "r"(a[2]), "r"(a[3]), "r"(b[0]), "r"(b[1]));
}

__device__ __forceinline__ void cp_async16(uint32_t dst, const void* src, int src_size) {
    asm volatile("cp.async.cg.shared.global [%0], [%1], 16, %2;"
                 :: "r"(dst), "l"(src), "r"(src_size) : "memory");
}
#define CP_COMMIT() asm volatile("cp.async.commit_group;" ::: "memory")
#define CP_WAIT(n)  asm volatile("cp.async.wait_group %0;" :: "n"(n) : "memory")

// smem: [row 0..127][k 0..15] raw fp32, row stride 24 (conflict-free LDS.64),
// TRIPLE buffered: A0|A1|A2|B0|B1|B2.
#define GSTRIDE 24
#define GBUF    (128 * GSTRIDE)       // 3072 floats = 12 KB
#define NSTG    3
#define GT_SMEM (2 * NSTG * GBUF * 4) // 72 KB

__device__ __forceinline__ void gemm_issue_stage(
    uint32_t sbase, int buf, const float* A, const float* W,
    int rowBase, int colBase, int N, int Kd, int kb, int tid)
{
    uint32_t aAddr = sbase + (uint32_t)(buf * GBUF * 4);
    uint32_t bAddr = sbase + (uint32_t)((NSTG * GBUF + buf * GBUF) * 4);
    #pragma unroll
    for (int i = 0; i < 2; i++) {
        int c   = tid + i * 256;
        int row = c >> 2, k4 = c & 3;
        int kg  = kb + k4 * 4;
        int ok  = (kg < Kd) ? 16 : 0;          // Kd % 4 == 0 -> chunk all-or-none
        uint32_t dst = (uint32_t)(row * (GSTRIDE * 4) + k4 * 16);
        cp_async16(aAddr + dst, A + (long)(rowBase + row) * Kd + kg, ok);
        int wr = colBase + row;
        int wc = (wr < N) ? wr : (N - 1);
        cp_async16(bAddr + dst, W + (long)wc * Kd + kg, (wr < N) ? ok : 0);
    }
}

__global__ __launch_bounds__(256) void sgemm_tc(
    const float* __restrict__ Abase, long sA,
    const float* __restrict__ Wbase, long sW,
    float* __restrict__ Cbase, long sC,
    const float* __restrict__ Xbase, long sX,
    int N, int Kd, int epi)
{
    int z = blockIdx.z;
    int Me = g_cnt[z];
    int rowBase = blockIdx.y * 128;
    if (rowBase >= Me) return;
    int colBase = blockIdx.x * 128;

    extern __shared__ __align__(16) float sdyn[];

    const float* A = Abase + (long)z * sA;
    const float* W = Wbase + (long)z * sW;
    float*       C = Cbase + (long)z * sC;
    const float* X = Xbase ? (Xbase + (long)z * sX) : nullptr;

    int tid  = threadIdx.x;
    int wid  = tid >> 5, lane = tid & 31;
    int gid  = lane >> 2, tig = lane & 3;      // mma fragment coords
    int warpM = wid & 3, warpN = wid >> 2;     // 4 x 2 warp grid
    int m0 = warpM * 32;                       // warp tile 32 x 64
    int n0 = warpN * 64;

    uint32_t sbase;
    asm("{ .reg .u64 t; cvta.to.shared.u64 t, %1; cvt.u32.u64 %0, t; }"
        : "=r"(sbase) : "l"((const void*)sdyn));

    float acc[2][8][4];
    #pragma unroll
    for (int i = 0; i < 2; i++)
        #pragma unroll
        for (int j = 0; j < 8; j++)
            #pragma unroll
            for (int q = 0; q < 4; q++) acc[i][j][q] = 0.f;

    int nstages = (Kd + 15) >> 4;
    int kk = 2 * tig;                           // k-pair base for this thread

    gemm_issue_stage(sbase, 0, A, W, rowBase, colBase, N, Kd, 0, tid);
    CP_COMMIT();
    if (nstages > 1) {
        gemm_issue_stage(sbase, 1, A, W, rowBase, colBase, N, Kd, 16, tid);
        CP_COMMIT();
    }

    for (int st = 0; st < nstages; st++) {
        // prefetch stage st+2 into buffer (st+2)%3 (consumed at st-1, synced)
        if (st + 2 < nstages) {
            gemm_issue_stage(sbase, (st + 2) % NSTG, A, W, rowBase, colBase,
                             N, Kd, (st + 2) << 4, tid);
            CP_COMMIT();
            CP_WAIT(2);               // stages st+1, st+2 pending -> st ready
        } else if (st + 1 < nstages) {
            CP_WAIT(1);               // stage st+1 pending -> st ready
        } else {
            CP_WAIT(0);
        }
        __syncthreads();

        const float* As = sdyn + (st % NSTG) * GBUF;
        const float* Bs = sdyn + NSTG * GBUF + (st % NSTG) * GBUF;

        // single k16 step: split raw floats to fp16 hi/lo in registers
        uint32_t aH[2][4], aL[2][4];
        #pragma unroll
        for (int mf = 0; mf < 2; mf++) {
            int mr0 = (m0 + mf * 16 + gid) * GSTRIDE;
            int mr1 = mr0 + 8 * GSTRIDE;
            split_h2(*(const float2*)(As + mr0 + kk),     aH[mf][0], aL[mf][0]);
            split_h2(*(const float2*)(As + mr1 + kk),     aH[mf][1], aL[mf][1]);
            split_h2(*(const float2*)(As + mr0 + kk + 8), aH[mf][2], aL[mf][2]);
            split_h2(*(const float2*)(As + mr1 + kk + 8), aH[mf][3], aL[mf][3]);
        }
        #pragma unroll
        for (int nf = 0; nf < 8; nf++) {
            int nr = (n0 + nf * 8 + gid) * GSTRIDE;
            uint32_t bh[2], bl[2];
            split_h2(*(const float2*)(Bs + nr + kk),     bh[0], bl[0]);
            split_h2(*(const float2*)(Bs + nr + kk + 8), bh[1], bl[1]);
            mma_f16(acc[0][nf], aH[0], bh);
            mma_f16(acc[1][nf], aH[1], bh);
            mma_f16(acc[0][nf], aL[0], bh);
            mma_f16(acc[1][nf], aL[1], bh);
            mma_f16(acc[0][nf], aH[0], bl);
            mma_f16(acc[1][nf], aH[1], bl);
        }
        __syncthreads();
    }

    // ---- epilogue (same C fragment layout) ----
    #pragma unroll
    for (int mf = 0; mf < 2; mf++) {
        #pragma unroll
        for (int nf = 0; nf < 8; nf++) {
            #pragma unroll
            for (int q = 0; q < 4; q++) {
                int rr = rowBase + m0 + mf * 16 + gid + (q >> 1) * 8;
                int cc = colBase + n0 + nf * 8 + 2 * tig + (q & 1);
                if (rr < Me && cc < N) {
                    float v = acc[mf][nf][q];
                    long idx = (long)rr * N + cc;
                    if (epi == EPI_SILU)         v = v * (1.f / (1.f + expf(-v)));
                    else if (epi == EPI_SIGMOID) v = 1.f / (1.f + expf(-v));
                    else                         v = v * X[idx];
                    C[idx] = v;
                }
            }
        }
    }
}

// ---------------- K5: combine (res + post, gated sum over experts) -------
__global__ void combine_kernel(const float* __restrict__ stream,
                               float* __restrict__ out)
{
    int t = blockIdx.x;
    int b = t >> 10, tt = t & 1023;
    int tid = threadIdx.x;      // 256
    __shared__ float cres[16];
    __shared__ float pc[KX][4];
    __shared__ float gsh[KX];
    __shared__ int   posh[KX];

    if (tid < KX) {
        gsh[tid]  = g_gate[tid][t];
        posh[tid] = g_pos[tid][t];
    }
    __syncthreads();
    if (tid < 16) {
        float s = 0.f;
        for (int kk = 0; kk < KX; kk++) {
            int p = posh[kk];
            if (p >= 0) s += gsh[kk] * g_Hres[kk][p][tid];
        }
        cres[tid] = s;
    } else if (tid >= 32 && tid < 32 + KX * 4) {
        int idx = tid - 32; int kk = idx >> 2, i = idx & 3;
        int p = posh[kk];
        pc[kk][i] = (p >= 0) ? gsh[kk] * g_Hpost[kk][p][i] : 0.f;
    }
    __syncthreads();

    for (int d = tid; d < D_; d += 256) {
        float sj[4];
        #pragma unroll
        for (int j = 0; j < 4; j++)
            sj[j] = stream[(((long)(b * N_ + j)) * T_ + tt) * D_ + d];
        float r[4];
        #pragma unroll
        for (int i = 0; i < 4; i++)
            r[i] = cres[i * 4 + 0] * sj[0] + cres[i * 4 + 1] * sj[1]
                 + cres[i * 4 + 2] * sj[2] + cres[i * 4 + 3] * sj[3];
        for (int kk = 0; kk < KX; kk++) {
            int p = posh[kk];
            if (p >= 0) {
                float oe = g_oute[kk][p][d];
                #pragma unroll
                for (int i = 0; i < 4; i++) r[i] += pc[kk][i] * oe;
            }
        }
        #pragma unroll
        for (int i = 0; i < 4; i++)
            out[(((long)(b * N_ + i)) * T_ + tt) * D_ + d] = r[i];
    }
}

// ---------------- launch ----------------
extern "C" void kernel_launch(void* const* d_in, const int* in_sizes, int n_in,
                              void* d_out, int out_size)
{
    const float* stream    = (const float*)d_in[0];
    const float* norm_w    = (const float*)d_in[1];
    const float* phi_pre   = (const float*)d_in[2];
    const float* phi_post  = (const float*)d_in[3];
    const float* phi_res   = (const float*)d_in[4];
    const float* b_pre     = (const float*)d_in[5];
    const float* b_post    = (const float*)d_in[6];
    const float* b_res     = (const float*)d_in[7];
    const float* alpha_pre = (const float*)d_in[8];
    const float* alpha_post= (const float*)d_in[9];
    const float* alpha_res = (const float*)d_in[10];
    const float* snw       = (const float*)d_in[11];
    const float* wd        = (const float*)d_in[12];
    const float* wu        = (const float*)d_in[13];
    const float* wg        = (const float*)d_in[14];
    const float* wup       = (const float*)d_in[15];
    const float* wdn       = (const float*)d_in[16];
    const float* rw        = (const float*)d_in[17];
    float* out = (float*)d_out;

    float *p_h, *p_s1, *p_g, *p_t1, *p_t2, *p_oe;
    cudaGetSymbolAddress((void**)&p_h,  g_h);
    cudaGetSymbolAddress((void**)&p_s1, g_s1);
    cudaGetSymbolAddress((void**)&p_g,  g_gsig);
    cudaGetSymbolAddress((void**)&p_t1, g_t1);
    cudaGetSymbolAddress((void**)&p_t2, g_t2);
    cudaGetSymbolAddress((void**)&p_oe, g_oute);

    cudaFuncSetAttribute(sgemm_tc, cudaFuncAttributeMaxDynamicSharedMemorySize, GT_SMEM);

    zero_cnt_kernel<<<1, 32>>>();
    routing_kernel<<<MTOK, 128>>>(stream, rw, out);
    xn_kernel<<<MTOK, 256>>>(stream);
    mhc_part<<<dim3(16, KX, KSPLIT), 256>>>(norm_w, phi_pre, phi_post, phi_res);
    mhc_epi<<<dim3(16, KX), 128>>>(b_pre, b_post, b_res,
                                   alpha_pre, alpha_post, alpha_res);
    he_kernel<<<dim3(KX, MTOK), 128>>>(stream, snw);

    long sHD = (long)MTOK * D_;
    long sHF = (long)MTOK * DFFN;

    // s1 = silu(h @ wd^T)
    sgemm_tc<<<dim3(4, 16, KX), 256, GT_SMEM>>>(p_h, sHD, wd + (long)D_ * D_,
                                                (long)D_ * D_, p_s1, sHD,
                                                nullptr, 0, D_, D_, EPI_SILU);
    // g = sigmoid(s1 @ wu^T)
    sgemm_tc<<<dim3(4, 16, KX), 256, GT_SMEM>>>(p_s1, sHD, wu + (long)D_ * D_,
                                                (long)D_ * D_, p_g, sHD,
                                                nullptr, 0, D_, D_, EPI_SIGMOID);
    // t1 = silu(h @ gate^T)
    sgemm_tc<<<dim3(7, 16, KX), 256, GT_SMEM>>>(p_h, sHD, wg + (long)DFFN * D_,
                                                (long)DFFN * D_, p_t1, sHF,
                                                nullptr, 0, DFFN, D_, EPI_SILU);
    // t2 = (h @ up^T) * t1
    sgemm_tc<<<dim3(7, 16, KX), 256, GT_SMEM>>>(p_h, sHD, wup + (long)DFFN * D_,
                                                (long)DFFN * D_, p_t2, sHF,
                                                p_t1, sHF, DFFN, D_, EPI_MUL);
    // out_e = (t2 @ down^T) * g
    sgemm_tc<<<dim3(4, 16, KX), 256, GT_SMEM>>>(p_t2, sHF, wdn + (long)D_ * DFFN,
                                                (long)D_ * DFFN, p_oe, sHD,
                                                p_g, sHD, D_, DFFN, EPI_MUL);

    combine_kernel<<<MTOK, 256>>>(stream, out);
}

// round 14
// speedup vs baseline: 1.5202x; 1.0238x over previous
#include <cuda_runtime.h>
#include <cuda_fp16.h>
#include <math.h>
#include <stdint.h>

#define B_   2
#define N_   4
#define T_   1024
#define D_   512
#define E_   16
#define KX   15          // computed experts (1..15)
#define DFFN 828
#define ND   2048        // N_*D_
#define MTOK 2048        // B_*T_
#define KSPLIT 32        // split-K factor for MHC projection

// ---------------- scratch (device globals; no allocation) ----------------
__device__ float g_xn[MTOK * ND];
__device__ int   g_cnt[KX];
__device__ int   g_idx[KX][MTOK];
__device__ int   g_pos[KX][MTOK];
__device__ float g_rs[(long)KX * 16 * 24 * KSPLIT * 128];
__device__ float g_Hpre[KX][MTOK][4];
__device__ float g_Hpost[KX][MTOK][4];
__device__ float g_Hres[KX][MTOK][16];
__device__ float g_gate[KX][MTOK];
__device__ float g_h[KX][MTOK][D_];
__device__ float g_s1[KX][MTOK][D_];
__device__ float g_gsig[KX][MTOK][D_];
__device__ float g_t1[KX][MTOK][DFFN];
__device__ float g_t2[KX][MTOK][DFFN];
__device__ float g_oute[KX][MTOK][D_];

__device__ __forceinline__ float sigmoidf_(float x) { return 1.f / (1.f + expf(-x)); }

__device__ __forceinline__ float block_reduce_sum(float v, float* sbuf) {
    int tid = threadIdx.x;
    #pragma unroll
    for (int o = 16; o > 0; o >>= 1) v += __shfl_down_sync(0xffffffffu, v, o);
    if ((tid & 31) == 0) sbuf[tid >> 5] = v;
    __syncthreads();
    int nw = blockDim.x >> 5;
    float r = (tid < nw) ? sbuf[tid] : 0.f;
    if (tid < 32) {
        #pragma unroll
        for (int o = 16; o > 0; o >>= 1) r += __shfl_down_sync(0xffffffffu, r, o);
        if (tid == 0) sbuf[0] = r;
    }
    __syncthreads();
    return sbuf[0];
}

// ---------------- K-1: zero per-expert counters ---------------------------
__global__ void zero_cnt_kernel() {
    if (threadIdx.x < KX) g_cnt[threadIdx.x] = 0;
}

// ---------------- K0: routing + compaction lists --------------------------
__global__ void routing_kernel(const float* __restrict__ stream,
                               const float* __restrict__ router_w,
                               float* __restrict__ out)
{
    int t = blockIdx.x;
    int b = t >> 10, tt = t & 1023;
    int tid = threadIdx.x;           // 128
    __shared__ float sred[E_][128];

    float acc[E_];
    #pragma unroll
    for (int e = 0; e < E_; e++) acc[e] = 0.f;

    for (int d = tid; d < D_; d += 128) {
        float ri = 0.f;
        #pragma unroll
        for (int n = 0; n < N_; n++)
            ri += stream[(((long)(b * N_ + n)) * T_ + tt) * D_ + d];
        ri *= 0.25f;
        #pragma unroll
        for (int e = 0; e < E_; e++) acc[e] += ri * router_w[e * D_ + d];
    }
    #pragma unroll
    for (int e = 0; e < E_; e++) sred[e][tid] = acc[e];
    __syncthreads();
    for (int s = 64; s > 0; s >>= 1) {
        if (tid < s) {
            #pragma unroll
            for (int e = 0; e < E_; e++) sred[e][tid] += sred[e][tid + s];
        }
        __syncthreads();
    }

    if (tid == 0) {
        float probs[E_];
        float mx = -1e30f;
        for (int e = 0; e < E_; e++) mx = fmaxf(mx, sred[e][0]);
        float ssum = 0.f;
        for (int e = 0; e < E_; e++) { probs[e] = expf(sred[e][0] - mx); ssum += probs[e]; }
        float inv = 1.f / ssum;
        for (int e = 0; e < E_; e++) probs[e] *= inv;

        int order[E_];
        for (int e = 0; e < E_; e++) order[e] = e;
        for (int i = 1; i < E_; i++) {
            int oi = order[i]; float p = probs[oi]; int j = i - 1;
            while (j >= 0 && probs[order[j]] < p) { order[j + 1] = order[j]; j--; }
            order[j + 1] = oi;
        }
        float gate[E_];
        for (int e = 0; e < E_; e++) gate[e] = 0.f;
        float cum = 0.f;
        for (int i = 0; i < E_; i++) {
            float p = probs[order[i]];
            bool m = (i == 0) || ((cum < 0.8f) && (i < 4));
            if (m) gate[order[i]] = p;
            cum += p;
        }
        float lp = 0.f;
        for (int e = 0; e < E_; e++)
            if (gate[e] > 0.f) lp += fmaxf(logf(probs[e]), -10.f);

        float* out_gate = out + (long)B_ * N_ * T_ * D_;
        float* out_lp   = out_gate + (long)B_ * T_ * E_;
        for (int e = 0; e < E_; e++) out_gate[(long)t * E_ + e] = gate[e];
        out_lp[t] = lp;
        for (int k = 0; k < KX; k++) {
            float gk = gate[k + 1];
            g_gate[k][t] = gk;
            if (gk > 0.f) {
                int p = atomicAdd(&g_cnt[k], 1);
                g_idx[k][p] = t;
                g_pos[k][t] = p;
            } else {
                g_pos[k][t] = -1;
            }
        }
    }
}

// ---------------- K1: xn = RMSNorm over nd of transposed stream ----------
__global__ void xn_kernel(const float* __restrict__ stream)
{
    int t = blockIdx.x;
    int b = t >> 10, tt = t & 1023;
    int tid = threadIdx.x;           // 256
    __shared__ float sbuf[32];
    float v[8]; float ss = 0.f;
    #pragma unroll
    for (int i = 0; i < 8; i++) {
        int j = tid + i * 256;
        int n = j >> 9, d = j & 511;
        float x = stream[(((long)(b * N_ + n)) * T_ + tt) * D_ + d];
        v[i] = x; ss += x * x;
    }
    float tot = block_reduce_sum(ss, sbuf);
    float rms = rsqrtf(tot * (1.f / ND) + 1e-8f);
    #pragma unroll
    for (int i = 0; i < 8; i++)
        g_xn[(long)t * ND + tid + i * 256] = v[i] * rms;
}

// ---------------- K2a: MHC projection partials (split-K) -----------------
__global__ __launch_bounds__(256) void mhc_part(
    const float* __restrict__ norm_w,
    const float* __restrict__ phi_pre, const float* __restrict__ phi_post,
    const float* __restrict__ phi_res)
{
    int tile = blockIdx.x;
    int k = blockIdx.y; int e = k + 1;
    int ks = blockIdx.z;
    int t0 = tile * 128;
    int cnt = g_cnt[k];
    if (t0 >= cnt) return;
    int tid = threadIdx.x;

    __shared__ int   tok[128];
    __shared__ float xs[32][129];
    __shared__ float ws[32][25];

    if (tid < 128) {
        int s = t0 + tid;
        tok[tid] = (s < cnt) ? g_idx[k][s] : g_idx[k][0];
    }
    __syncthreads();

    int r = tid & 63;
    int q = tid >> 6;

    float acc[2][6];
    #pragma unroll
    for (int a = 0; a < 2; a++)
        #pragma unroll
        for (int m = 0; m < 6; m++) acc[a][m] = 0.f;

    const int kbeg = ks * (ND / KSPLIT);
    const int kend = kbeg + (ND / KSPLIT);
    for (int kb = kbeg; kb < kend; kb += 32) {
        #pragma unroll
        for (int i = 0; i < 16; i++) {
            int lin = tid + i * 256;
            int trow = lin >> 5, tcol = lin & 31;
            xs[tcol][trow] = g_xn[(long)tok[trow] * ND + kb + tcol];
        }
        #pragma unroll
        for (int i = 0; i < 3; i++) {
            int lin = tid + i * 256;
            int jrow = lin >> 5, kcol = lin & 31;
            int gk = kb + kcol;
            const float* wr;
            if (jrow < 4)      wr = phi_pre  + (long)(e * 4  + jrow)       * ND;
            else if (jrow < 8) wr = phi_post + (long)(e * 4  + (jrow - 4)) * ND;
            else               wr = phi_res  + (long)(e * 16 + (jrow - 8)) * ND;
            ws[kcol][jrow] = wr[gk] * norm_w[(long)e * ND + gk];
        }
        __syncthreads();
        #pragma unroll
        for (int kk = 0; kk < 32; kk++) {
            float x0 = xs[kk][r], x1 = xs[kk][r + 64];
            #pragma unroll
            for (int m = 0; m < 6; m++) {
                float w = ws[kk][q + m * 4];
                acc[0][m] += x0 * w;
                acc[1][m] += x1 * w;
            }
        }
        __syncthreads();
    }

    long base = ((long)(k * 16 + tile)) * 24;
    #pragma unroll
    for (int m = 0; m < 6; m++) {
        int j = q + m * 4;
        long o = ((base + j) * KSPLIT + ks) * 128;
        g_rs[o + r]      = acc[0][m];
        g_rs[o + r + 64] = acc[1][m];
    }
}

// ---------------- K2b: sum partials + sigmoid/sinkhorn epilogue ----------
__global__ void mhc_epi(
    const float* __restrict__ b_pre, const float* __restrict__ b_post,
    const float* __restrict__ b_res,
    const float* __restrict__ alpha_pre, const float* __restrict__ alpha_post,
    const float* __restrict__ alpha_res)
{
    int tile = blockIdx.x;
    int k = blockIdx.y; int e = k + 1;
    int cnt = g_cnt[k];
    int slot = tile * 128 + threadIdx.x;
    if (slot >= cnt) return;

    float rsv[24];
    long base = ((long)(k * 16 + tile)) * 24;
    #pragma unroll
    for (int j = 0; j < 24; j++) {
        long o = (base + j) * KSPLIT * 128 + threadIdx.x;
        float s = 0.f;
        #pragma unroll
        for (int ks = 0; ks < KSPLIT; ks++) s += g_rs[o + (long)ks * 128];
        rsv[j] = s;
    }

    float ap  = alpha_pre[e];
    float apo = alpha_post[e];
    float ar  = alpha_res[e];
    #pragma unroll
    for (int n = 0; n < 4; n++) {
        g_Hpre[k][slot][n]  = sigmoidf_(ap  * rsv[n]     + b_pre[e * 4 + n]);
        g_Hpost[k][slot][n] = 2.f * sigmoidf_(apo * rsv[4 + n] + b_post[e * 4 + n]);
    }
    float m[4][4];
    #pragma unroll
    for (int i = 0; i < 4; i++)
        #pragma unroll
        for (int j = 0; j < 4; j++)
            m[i][j] = expf(ar * rsv[8 + i * 4 + j] + b_res[e * 16 + i * 4 + j]);
    #pragma unroll
    for (int it = 0; it < 6; it++) {
        #pragma unroll
        for (int i = 0; i < 4; i++) {
            float s = m[i][0] + m[i][1] + m[i][2] + m[i][3];
            float iv = 1.f / s;
            m[i][0] *= iv; m[i][1] *= iv; m[i][2] *= iv; m[i][3] *= iv;
        }
        #pragma unroll
        for (int j = 0; j < 4; j++) {
            float s = m[0][j] + m[1][j] + m[2][j] + m[3][j];
            float iv = 1.f / s;
            m[0][j] *= iv; m[1][j] *= iv; m[2][j] *= iv; m[3][j] *= iv;
        }
    }
    #pragma unroll
    for (int i = 0; i < 4; i++)
        #pragma unroll
        for (int j = 0; j < 4; j++)
            g_Hres[k][slot][i * 4 + j] = m[i][j];
}

// ---------------- K3: h = RMSNorm(H_pre @ stream) * swiglu_norm_w --------
__global__ void he_kernel(const float* __restrict__ stream,
                          const float* __restrict__ snw)
{
    int k = blockIdx.x;
    int slot = blockIdx.y;
    if (slot >= g_cnt[k]) return;
    int t = g_idx[k][slot];
    int b = t >> 10, tt = t & 1023;
    int tid = threadIdx.x;
    __shared__ float sbuf[32];

    float hp[4];
    #pragma unroll
    for (int n = 0; n < 4; n++) hp[n] = g_Hpre[k][slot][n];

    float v[4]; float ss = 0.f;
    #pragma unroll
    for (int i = 0; i < 4; i++) {
        int d = tid + i * 128;
        float s = 0.f;
        #pragma unroll
        for (int n = 0; n < 4; n++)
            s += hp[n] * stream[(((long)(b * N_ + n)) * T_ + tt) * D_ + d];
        v[i] = s; ss += s * s;
    }
    float tot = block_reduce_sum(ss, sbuf);
    float rms = rsqrtf(tot * (1.f / D_) + 1e-8f);
    int e = k + 1;
    #pragma unroll
    for (int i = 0; i < 4; i++) {
        int d = tid + i * 128;
        g_h[k][slot][d] = v[i] * rms * snw[e * D_ + d];
    }
}

// ---------------- 3x split-FP16 mma.sync GEMM, cp.async pipeline ---------
// C[M,N] = epi(A[M,Kd] @ W[N,Kd]^T), per expert z, tile 128x128.
#define EPI_SILU    0
#define EPI_SIGMOID 1
#define EPI_MUL     2

// split x into fp16 hi + fp16 lo pairs (2 elements at a time)
__device__ __forceinline__ void split_h2(float2 v, uint32_t& hi, uint32_t& lo) {
    __half2 h = __float22half2_rn(v);
    float2 back = __half22float2(h);
    __half2 l = __float22half2_rn(make_float2(v.x - back.x, v.y - back.y));
    hi = *(uint32_t*)&h;
    lo = *(uint32_t*)&l;
}

__device__ __forceinline__ void mma_f16(float* c, const uint32_t* a, const uint32_t* b) {
    asm volatile(
        "mma.sync.aligned.m16n8k16.row.col.f32.f16.f16.f32 "
        "{%0,%1,%2,%3}, {%4,%5,%6,%7}, {%8,%9}, {%0,%1,%2,%3};"
        : "+f"(c[0]), "+f"(c[1]), "+f"(c[2]), "+f"(c[3])
        : "r"(a[0]), "r"(a[1]), "r"(a[2]), "r"(a[3]), "r"(b[0]), "r"(b[1]));
}

__device__ __forceinline__ void cp_async16(uint32_t dst, const void* src, int src_size) {
    asm volatile("cp.async.cg.shared.global [%0], [%1], 16, %2;"
                 :: "r"(dst), "l"(src), "r"(src_size) : "memory");
}
#define CP_COMMIT() asm volatile("cp.async.commit_group;" ::: "memory")
#define CP_WAIT(n)  asm volatile("cp.async.wait_group %0;" :: "n"(n) : "memory")

// smem: [row 0..127][k 0..15] raw fp32, row stride 24 floats (conflict-free:
// (gid*96 + tig*8) mod 128 distinct per half-warp), double buffered A|B.
#define GSTRIDE 24
#define GBUF    (128 * GSTRIDE)       // 3072 floats = 12 KB
#define GT_SMEM (4 * GBUF * 4)        // A0|A1|B0|B1 = 48 KB

__device__ __forceinline__ void gemm_issue_stage(
    uint32_t sbase, int buf, const float* A, const float* W,
    int rowBase, int colBase, int N, int Kd, int kb, int tid)
{
    uint32_t aAddr = sbase + (uint32_t)(buf * GBUF * 4);
    uint32_t bAddr = sbase + (uint32_t)((2 * GBUF + buf * GBUF) * 4);
    #pragma unroll
    for (int i = 0; i < 2; i++) {
        int c   = tid + i * 256;
        int row = c >> 2, k4 = c & 3;
        int kg  = kb + k4 * 4;
        int ok  = (kg < Kd) ? 16 : 0;          // Kd % 4 == 0 -> chunk all-or-none
        uint32_t dst = (uint32_t)(row * (GSTRIDE * 4) + k4 * 16);
        cp_async16(aAddr + dst, A + (long)(rowBase + row) * Kd + kg, ok);
        int wr = colBase + row;
        int wc = (wr < N) ? wr : (N - 1);
        cp_async16(bAddr + dst, W + (long)wc * Kd + kg, (wr < N) ? ok : 0);
    }
}

__global__ __launch_bounds__(256) void sgemm_tc(
    const float* __restrict__ Abase, long sA,
    const float* __restrict__ Wbase, long sW,
    float* __restrict__ Cbase, long sC,
    const float* __restrict__ Xbase, long sX,
    int N, int Kd, int epi)
{
    int z = blockIdx.z;
    int Me = g_cnt[z];
    int rowBase = blockIdx.y * 128;
    if (rowBase >= Me) return;
    int colBase = blockIdx.x * 128;

    extern __shared__ __align__(16) float sdyn[];

    const float* A = Abase + (long)z * sA;
    const float* W = Wbase + (long)z * sW;
    float*       C = Cbase + (long)z * sC;
    const float* X = Xbase ? (Xbase + (long)z * sX) : nullptr;

    int tid  = threadIdx.x;
    int wid  = tid >> 5, lane = tid & 31;
    int gid  = lane >> 2, tig = lane & 3;      // mma fragment coords
    int warpM = wid & 3, warpN = wid >> 2;     // 4 x 2 warp grid
    int m0 = warpM * 32;                       // warp tile 32 x 64
    int n0 = warpN * 64;

    uint32_t sbase;
    asm("{ .reg .u64 t; cvta.to.shared.u64 t, %1; cvt.u32.u64 %0, t; }"
        : "=r"(sbase) : "l"((const void*)sdyn));

    float acc[2][8][4];
    #pragma unroll
    for (int i = 0; i < 2; i++)
        #pragma unroll
        for (int j = 0; j < 8; j++)
            #pragma unroll
            for (int q = 0; q < 4; q++) acc[i][j][q] = 0.f;

    int nstages = (Kd + 15) >> 4;
    int kk = 2 * tig;                           // k-pair base for this thread

    gemm_issue_stage(sbase, 0, A, W, rowBase, colBase, N, Kd, 0, tid);
    CP_COMMIT();

    for (int st = 0; st < nstages; st++) {
        if (st + 1 < nstages) {
            gemm_issue_stage(sbase, (st + 1) & 1, A, W, rowBase, colBase, N, Kd,
                             (st + 1) << 4, tid);
            CP_COMMIT();
            CP_WAIT(1);
        } else {
            CP_WAIT(0);
        }
        __syncthreads();

        const float* As = sdyn + (st & 1) * GBUF;
        const float* Bs = sdyn + 2 * GBUF + (st & 1) * GBUF;

        // single k16 step: split raw floats to fp16 hi/lo in registers
        uint32_t aH[2][4], aL[2][4];
        #pragma unroll
        for (int mf = 0; mf < 2; mf++) {
            int mr0 = (m0 + mf * 16 + gid) * GSTRIDE;
            int mr1 = mr0 + 8 * GSTRIDE;
            split_h2(*(const float2*)(As + mr0 + kk),     aH[mf][0], aL[mf][0]);
            split_h2(*(const float2*)(As + mr1 + kk),     aH[mf][1], aL[mf][1]);
            split_h2(*(const float2*)(As + mr0 + kk + 8), aH[mf][2], aL[mf][2]);
            split_h2(*(const float2*)(As + mr1 + kk + 8), aH[mf][3], aL[mf][3]);
        }
        #pragma unroll
        for (int nf = 0; nf < 8; nf++) {
            int nr = (n0 + nf * 8 + gid) * GSTRIDE;
            uint32_t bh[2], bl[2];
            split_h2(*(const float2*)(Bs + nr + kk),     bh[0], bl[0]);
            split_h2(*(const float2*)(Bs + nr + kk + 8), bh[1], bl[1]);
            mma_f16(acc[0][nf], aH[0], bh);
            mma_f16(acc[1][nf], aH[1], bh);
            mma_f16(acc[0][nf], aL[0], bh);
            mma_f16(acc[1][nf], aL[1], bh);
            mma_f16(acc[0][nf], aH[0], bl);
            mma_f16(acc[1][nf], aH[1], bl);
        }
        __syncthreads();
    }

    // ---- epilogue (same C fragment layout as k8) ----
    #pragma unroll
    for (int mf = 0; mf < 2; mf++) {
        #pragma unroll
        for (int nf = 0; nf < 8; nf++) {
            #pragma unroll
            for (int q = 0; q < 4; q++) {
                int rr = rowBase + m0 + mf * 16 + gid + (q >> 1) * 8;
                int cc = colBase + n0 + nf * 8 + 2 * tig + (q & 1);
                if (rr < Me && cc < N) {
                    float v = acc[mf][nf][q];
                    long idx = (long)rr * N + cc;
                    if (epi == EPI_SILU)         v = v * (1.f / (1.f + expf(-v)));
                    else if (epi == EPI_SIGMOID) v = 1.f / (1.f + expf(-v));
                    else                         v = v * X[idx];
                    C[idx] = v;
                }
            }
        }
    }
}

// ---------------- K5: combine (res + post, gated sum over experts) -------
__global__ void combine_kernel(const float* __restrict__ stream,
                               float* __restrict__ out)
{
    int t = blockIdx.x;
    int b = t >> 10, tt = t & 1023;
    int tid = threadIdx.x;      // 256
    __shared__ float cres[16];
    __shared__ float pc[KX][4];
    __shared__ float gsh[KX];
    __shared__ int   posh[KX];

    if (tid < KX) {
        gsh[tid]  = g_gate[tid][t];
        posh[tid] = g_pos[tid][t];
    }
    __syncthreads();
    if (tid < 16) {
        float s = 0.f;
        for (int kk = 0; kk < KX; kk++) {
            int p = posh[kk];
            if (p >= 0) s += gsh[kk] * g_Hres[kk][p][tid];
        }
        cres[tid] = s;
    } else if (tid >= 32 && tid < 32 + KX * 4) {
        int idx = tid - 32; int kk = idx >> 2, i = idx & 3;
        int p = posh[kk];
        pc[kk][i] = (p >= 0) ? gsh[kk] * g_Hpost[kk][p][i] : 0.f;
    }
    __syncthreads();

    for (int d = tid; d < D_; d += 256) {
        float sj[4];
        #pragma unroll
        for (int j = 0; j < 4; j++)
            sj[j] = stream[(((long)(b * N_ + j)) * T_ + tt) * D_ + d];
        float r[4];
        #pragma unroll
        for (int i = 0; i < 4; i++)
            r[i] = cres[i * 4 + 0] * sj[0] + cres[i * 4 + 1] * sj[1]
                 + cres[i * 4 + 2] * sj[2] + cres[i * 4 + 3] * sj[3];
        for (int kk = 0; kk < KX; kk++) {
            int p = posh[kk];
            if (p >= 0) {
                float oe = g_oute[kk][p][d];
                #pragma unroll
                for (int i = 0; i < 4; i++) r[i] += pc[kk][i] * oe;
            }
        }
        #pragma unroll
        for (int i = 0; i < 4; i++)
            out[(((long)(b * N_ + i)) * T_ + tt) * D_ + d] = r[i];
    }
}

// ---------------- launch ----------------
extern "C" void kernel_launch(void* const* d_in, const int* in_sizes, int n_in,
                              void* d_out, int out_size)
{
    const float* stream    = (const float*)d_in[0];
    const float* norm_w    = (const float*)d_in[1];
    const float* phi_pre   = (const float*)d_in[2];
    const float* phi_post  = (const float*)d_in[3];
    const float* phi_res   = (const float*)d_in[4];
    const float* b_pre     = (const float*)d_in[5];
    const float* b_post    = (const float*)d_in[6];
    const float* b_res     = (const float*)d_in[7];
    const float* alpha_pre = (const float*)d_in[8];
    const float* alpha_post= (const float*)d_in[9];
    const float* alpha_res = (const float*)d_in[10];
    const float* snw       = (const float*)d_in[11];
    const float* wd        = (const float*)d_in[12];
    const float* wu        = (const float*)d_in[13];
    const float* wg        = (const float*)d_in[14];
    const float* wup       = (const float*)d_in[15];
    const float* wdn       = (const float*)d_in[16];
    const float* rw        = (const float*)d_in[17];
    float* out = (float*)d_out;

    float *p_h, *p_s1, *p_g, *p_t1, *p_t2, *p_oe;
    cudaGetSymbolAddress((void**)&p_h,  g_h);
    cudaGetSymbolAddress((void**)&p_s1, g_s1);
    cudaGetSymbolAddress((void**)&p_g,  g_gsig);
    cudaGetSymbolAddress((void**)&p_t1, g_t1);
    cudaGetSymbolAddress((void**)&p_t2, g_t2);
    cudaGetSymbolAddress((void**)&p_oe, g_oute);

    cudaFuncSetAttribute(sgemm_tc, cudaFuncAttributeMaxDynamicSharedMemorySize, GT_SMEM);

    zero_cnt_kernel<<<1, 32>>>();
    routing_kernel<<<MTOK, 128>>>(stream, rw, out);
    xn_kernel<<<MTOK, 256>>>(stream);
    mhc_part<<<dim3(16, KX, KSPLIT), 256>>>(norm_w, phi_pre, phi_post, phi_res);
    mhc_epi<<<dim3(16, KX), 128>>>(b_pre, b_post, b_res,
                                   alpha_pre, alpha_post, alpha_res);
    he_kernel<<<dim3(KX, MTOK), 128>>>(stream, snw);

    long sHD = (long)MTOK * D_;
    long sHF = (long)MTOK * DFFN;

    // s1 = silu(h @ wd^T)
    sgemm_tc<<<dim3(4, 16, KX), 256, GT_SMEM>>>(p_h, sHD, wd + (long)D_ * D_,
                                                (long)D_ * D_, p_s1, sHD,
                                                nullptr, 0, D_, D_, EPI_SILU);
    // g = sigmoid(s1 @ wu^T)
    sgemm_tc<<<dim3(4, 16, KX), 256, GT_SMEM>>>(p_s1, sHD, wu + (long)D_ * D_,
                                                (long)D_ * D_, p_g, sHD,
                                                nullptr, 0, D_, D_, EPI_SIGMOID);
    // t1 = silu(h @ gate^T)
    sgemm_tc<<<dim3(7, 16, KX), 256, GT_SMEM>>>(p_h, sHD, wg + (long)DFFN * D_,
                                                (long)DFFN * D_, p_t1, sHF,
                                                nullptr, 0, DFFN, D_, EPI_SILU);
    // t2 = (h @ up^T) * t1
    sgemm_tc<<<dim3(7, 16, KX), 256, GT_SMEM>>>(p_h, sHD, wup + (long)DFFN * D_,
                                                (long)DFFN * D_, p_t2, sHF,
                                                p_t1, sHF, DFFN, D_, EPI_MUL);
    // out_e = (t2 @ down^T) * g
    sgemm_tc<<<dim3(4, 16, KX), 256, GT_SMEM>>>(p_t2, sHF, wdn + (long)D_ * DFFN,
                                                (long)D_ * DFFN, p_oe, sHD,
                                                p_g, sHD, D_, DFFN, EPI_MUL);

    combine_kernel<<<MTOK, 256>>>(stream, out);
}

// round 15
// speedup vs baseline: 1.8583x; 1.2224x over previous
#include <cuda_runtime.h>
#include <cuda_fp16.h>
#include <math.h>
#include <stdint.h>

#define B_   2
#define N_   4
#define T_   1024
#define D_   512
#define E_   16
#define KX   15          // computed experts (1..15)
#define DFFN 828
#define ND   2048        // N_*D_
#define MTOK 2048        // B_*T_
#define KSPLIT 32        // split-K factor for MHC projection

// ---------------- scratch (device globals; no allocation) ----------------
__device__ float g_xn[MTOK * ND];
__device__ int   g_cnt[KX];
__device__ int   g_idx[KX][MTOK];
__device__ int   g_pos[KX][MTOK];
__device__ float g_rs[(long)KX * 16 * 24 * KSPLIT * 128];
__device__ float g_Hpre[KX][MTOK][4];
__device__ float g_Hpost[KX][MTOK][4];
__device__ float g_Hres[KX][MTOK][16];
__device__ float g_gate[KX][MTOK];
__device__ float g_h[KX][MTOK][D_];
__device__ float g_s1[KX][MTOK][D_];
__device__ float g_gsig[KX][MTOK][D_];
__device__ float g_t1[KX][MTOK][DFFN];
__device__ float g_t2[KX][MTOK][DFFN];
__device__ float g_oute[KX][MTOK][D_];

__device__ __forceinline__ float sigmoidf_(float x) { return 1.f / (1.f + expf(-x)); }

__device__ __forceinline__ float block_reduce_sum(float v, float* sbuf) {
    int tid = threadIdx.x;
    #pragma unroll
    for (int o = 16; o > 0; o >>= 1) v += __shfl_down_sync(0xffffffffu, v, o);
    if ((tid & 31) == 0) sbuf[tid >> 5] = v;
    __syncthreads();
    int nw = blockDim.x >> 5;
    float r = (tid < nw) ? sbuf[tid] : 0.f;
    if (tid < 32) {
        #pragma unroll
        for (int o = 16; o > 0; o >>= 1) r += __shfl_down_sync(0xffffffffu, r, o);
        if (tid == 0) sbuf[0] = r;
    }
    __syncthreads();
    return sbuf[0];
}

// ---------------- K-1: zero per-expert counters ---------------------------
__global__ void zero_cnt_kernel() {
    if (threadIdx.x < KX) g_cnt[threadIdx.x] = 0;
}

// ---------------- K0: routing + compaction lists --------------------------
__global__ void routing_kernel(const float* __restrict__ stream,
                               const float* __restrict__ router_w,
                               float* __restrict__ out)
{
    int t = blockIdx.x;
    int b = t >> 10, tt = t & 1023;
    int tid = threadIdx.x;           // 128
    __shared__ float sred[E_][128];

    float acc[E_];
    #pragma unroll
    for (int e = 0; e < E_; e++) acc[e] = 0.f;

    for (int d = tid; d < D_; d += 128) {
        float ri = 0.f;
        #pragma unroll
        for (int n = 0; n < N_; n++)
            ri += stream[(((long)(b * N_ + n)) * T_ + tt) * D_ + d];
        ri *= 0.25f;
        #pragma unroll
        for (int e = 0; e < E_; e++) acc[e] += ri * router_w[e * D_ + d];
    }
    #pragma unroll
    for (int e = 0; e < E_; e++) sred[e][tid] = acc[e];
    __syncthreads();
    for (int s = 64; s > 0; s >>= 1) {
        if (tid < s) {
            #pragma unroll
            for (int e = 0; e < E_; e++) sred[e][tid] += sred[e][tid + s];
        }
        __syncthreads();
    }

    if (tid == 0) {
        float probs[E_];
        float mx = -1e30f;
        for (int e = 0; e < E_; e++) mx = fmaxf(mx, sred[e][0]);
        float ssum = 0.f;
        for (int e = 0; e < E_; e++) { probs[e] = expf(sred[e][0] - mx); ssum += probs[e]; }
        float inv = 1.f / ssum;
        for (int e = 0; e < E_; e++) probs[e] *= inv;

        int order[E_];
        for (int e = 0; e < E_; e++) order[e] = e;
        for (int i = 1; i < E_; i++) {
            int oi = order[i]; float p = probs[oi]; int j = i - 1;
            while (j >= 0 && probs[order[j]] < p) { order[j + 1] = order[j]; j--; }
            order[j + 1] = oi;
        }
        float gate[E_];
        for (int e = 0; e < E_; e++) gate[e] = 0.f;
        float cum = 0.f;
        for (int i = 0; i < E_; i++) {
            float p = probs[order[i]];
            bool m = (i == 0) || ((cum < 0.8f) && (i < 4));
            if (m) gate[order[i]] = p;
            cum += p;
        }
        float lp = 0.f;
        for (int e = 0; e < E_; e++)
            if (gate[e] > 0.f) lp += fmaxf(logf(probs[e]), -10.f);

        float* out_gate = out + (long)B_ * N_ * T_ * D_;
        float* out_lp   = out_gate + (long)B_ * T_ * E_;
        for (int e = 0; e < E_; e++) out_gate[(long)t * E_ + e] = gate[e];
        out_lp[t] = lp;
        for (int k = 0; k < KX; k++) {
            float gk = gate[k + 1];
            g_gate[k][t] = gk;
            if (gk > 0.f) {
                int p = atomicAdd(&g_cnt[k], 1);
                g_idx[k][p] = t;
                g_pos[k][t] = p;
            } else {
                g_pos[k][t] = -1;
            }
        }
    }
}

// ---------------- K1: xn = RMSNorm over nd of transposed stream ----------
__global__ void xn_kernel(const float* __restrict__ stream)
{
    int t = blockIdx.x;
    int b = t >> 10, tt = t & 1023;
    int tid = threadIdx.x;           // 256
    __shared__ float sbuf[32];
    float v[8]; float ss = 0.f;
    #pragma unroll
    for (int i = 0; i < 8; i++) {
        int j = tid + i * 256;
        int n = j >> 9, d = j & 511;
        float x = stream[(((long)(b * N_ + n)) * T_ + tt) * D_ + d];
        v[i] = x; ss += x * x;
    }
    float tot = block_reduce_sum(ss, sbuf);
    float rms = rsqrtf(tot * (1.f / ND) + 1e-8f);
    #pragma unroll
    for (int i = 0; i < 8; i++)
        g_xn[(long)t * ND + tid + i * 256] = v[i] * rms;
}

// ---------------- K2a: MHC projection partials (split-K) -----------------
__global__ __launch_bounds__(256, 4) void mhc_part(
    const float* __restrict__ norm_w,
    const float* __restrict__ phi_pre, const float* __restrict__ phi_post,
    const float* __restrict__ phi_res)
{
    int tile = blockIdx.x;
    int k = blockIdx.y; int e = k + 1;
    int ks = blockIdx.z;
    int t0 = tile * 128;
    int cnt = g_cnt[k];
    if (t0 >= cnt) return;
    int tid = threadIdx.x;

    __shared__ int   tok[128];
    __shared__ float xs[32][129];
    __shared__ float ws[32][25];

    if (tid < 128) {
        int s = t0 + tid;
        tok[tid] = (s < cnt) ? g_idx[k][s] : g_idx[k][0];
    }
    __syncthreads();

    int r = tid & 63;
    int q = tid >> 6;

    float acc[2][6];
    #pragma unroll
    for (int a = 0; a < 2; a++)
        #pragma unroll
        for (int m = 0; m < 6; m++) acc[a][m] = 0.f;

    const int kbeg = ks * (ND / KSPLIT);
    const int kend = kbeg + (ND / KSPLIT);
    for (int kb = kbeg; kb < kend; kb += 32) {
        #pragma unroll
        for (int i = 0; i < 16; i++) {
            int lin = tid + i * 256;
            int trow = lin >> 5, tcol = lin & 31;
            xs[tcol][trow] = g_xn[(long)tok[trow] * ND + kb + tcol];
        }
        #pragma unroll
        for (int i = 0; i < 3; i++) {
            int lin = tid + i * 256;
            int jrow = lin >> 5, kcol = lin & 31;
            int gk = kb + kcol;
            const float* wr;
            if (jrow < 4)      wr = phi_pre  + (long)(e * 4  + jrow)       * ND;
            else if (jrow < 8) wr = phi_post + (long)(e * 4  + (jrow - 4)) * ND;
            else               wr = phi_res  + (long)(e * 16 + (jrow - 8)) * ND;
            ws[kcol][jrow] = wr[gk] * norm_w[(long)e * ND + gk];
        }
        __syncthreads();
        #pragma unroll
        for (int kk = 0; kk < 32; kk++) {
            float x0 = xs[kk][r], x1 = xs[kk][r + 64];
            #pragma unroll
            for (int m = 0; m < 6; m++) {
                float w = ws[kk][q + m * 4];
                acc[0][m] += x0 * w;
                acc[1][m] += x1 * w;
            }
        }
        __syncthreads();
    }

    long base = ((long)(k * 16 + tile)) * 24;
    #pragma unroll
    for (int m = 0; m < 6; m++) {
        int j = q + m * 4;
        long o = ((base + j) * KSPLIT + ks) * 128;
        g_rs[o + r]      = acc[0][m];
        g_rs[o + r + 64] = acc[1][m];
    }
}

// ---------------- K2b: sum partials + sigmoid/sinkhorn epilogue ----------
__global__ void mhc_epi(
    const float* __restrict__ b_pre, const float* __restrict__ b_post,
    const float* __restrict__ b_res,
    const float* __restrict__ alpha_pre, const float* __restrict__ alpha_post,
    const float* __restrict__ alpha_res)
{
    int tile = blockIdx.x;
    int k = blockIdx.y; int e = k + 1;
    int cnt = g_cnt[k];
    int slot = tile * 128 + threadIdx.x;
    if (slot >= cnt) return;

    float rsv[24];
    long base = ((long)(k * 16 + tile)) * 24;
    #pragma unroll
    for (int j = 0; j < 24; j++) {
        long o = (base + j) * KSPLIT * 128 + threadIdx.x;
        float s = 0.f;
        #pragma unroll
        for (int ks = 0; ks < KSPLIT; ks++) s += g_rs[o + (long)ks * 128];
        rsv[j] = s;
    }

    float ap  = alpha_pre[e];
    float apo = alpha_post[e];
    float ar  = alpha_res[e];
    #pragma unroll
    for (int n = 0; n < 4; n++) {
        g_Hpre[k][slot][n]  = sigmoidf_(ap  * rsv[n]     + b_pre[e * 4 + n]);
        g_Hpost[k][slot][n] = 2.f * sigmoidf_(apo * rsv[4 + n] + b_post[e * 4 + n]);
    }
    float m[4][4];
    #pragma unroll
    for (int i = 0; i < 4; i++)
        #pragma unroll
        for (int j = 0; j < 4; j++)
            m[i][j] = expf(ar * rsv[8 + i * 4 + j] + b_res[e * 16 + i * 4 + j]);
    #pragma unroll
    for (int it = 0; it < 6; it++) {
        #pragma unroll
        for (int i = 0; i < 4; i++) {
            float s = m[i][0] + m[i][1] + m[i][2] + m[i][3];
            float iv = 1.f / s;
            m[i][0] *= iv; m[i][1] *= iv; m[i][2] *= iv; m[i][3] *= iv;
        }
        #pragma unroll
        for (int j = 0; j < 4; j++) {
            float s = m[0][j] + m[1][j] + m[2][j] + m[3][j];
            float iv = 1.f / s;
            m[0][j] *= iv; m[1][j] *= iv; m[2][j] *= iv; m[3][j] *= iv;
        }
    }
    #pragma unroll
    for (int i = 0; i < 4; i++)
        #pragma unroll
        for (int j = 0; j < 4; j++)
            g_Hres[k][slot][i * 4 + j] = m[i][j];
}

// ---------------- K3: h = RMSNorm(H_pre @ stream) * swiglu_norm_w --------
__global__ void he_kernel(const float* __restrict__ stream,
                          const float* __restrict__ snw)
{
    int k = blockIdx.x;
    int slot = blockIdx.y;
    if (slot >= g_cnt[k]) return;
    int t = g_idx[k][slot];
    int b = t >> 10, tt = t & 1023;
    int tid = threadIdx.x;
    __shared__ float sbuf[32];

    float hp[4];
    #pragma unroll
    for (int n = 0; n < 4; n++) hp[n] = g_Hpre[k][slot][n];

    float v[4]; float ss = 0.f;
    #pragma unroll
    for (int i = 0; i < 4; i++) {
        int d = tid + i * 128;
        float s = 0.f;
        #pragma unroll
        for (int n = 0; n < 4; n++)
            s += hp[n] * stream[(((long)(b * N_ + n)) * T_ + tt) * D_ + d];
        v[i] = s; ss += s * s;
    }
    float tot = block_reduce_sum(ss, sbuf);
    float rms = rsqrtf(tot * (1.f / D_) + 1e-8f);
    int e = k + 1;
    #pragma unroll
    for (int i = 0; i < 4; i++) {
        int d = tid + i * 128;
        g_h[k][slot][d] = v[i] * rms * snw[e * D_ + d];
    }
}

// ---------------- 2-pass split-FP16 mma.sync GEMM, cp.async pipeline -----
// C[M,N] = epi(A[M,Kd] @ W[N,Kd]^T): A split exactly (hi+lo), W rounded to
// fp16 (error ~2^-12 rel, zero-mean). 32 HMMA per stage per warp.
#define EPI_SILU    0
#define EPI_SIGMOID 1
#define EPI_MUL     2

// split x into fp16 hi + fp16 lo pairs (2 elements at a time)
__device__ __forceinline__ void split_h2(float2 v, uint32_t& hi, uint32_t& lo) {
    __half2 h = __float22half2_rn(v);
    float2 back = __half22float2(h);
    __half2 l = __float22half2_rn(make_float2(v.x - back.x, v.y - back.y));
    hi = *(uint32_t*)&h;
    lo = *(uint32_t*)&l;
}
__device__ __forceinline__ uint32_t cvt_h2(float2 v) {
    __half2 h = __float22half2_rn(v);
    return *(uint32_t*)&h;
}

__device__ __forceinline__ void mma_f16(float* c, const uint32_t* a, const uint32_t* b) {
    asm volatile(
        "mma.sync.aligned.m16n8k16.row.col.f32.f16.f16.f32 "
        "{%0,%1,%2,%3}, {%4,%5,%6,%7}, {%8,%9}, {%0,%1,%2,%3};"
        : "+f"(c[0]), "+f"(c[1]), "+f"(c[2]), "+f"(c[3])
        : "r"(a[0]), "r"(a[1]), "r"(a[2]), "r"(a[3]), "r"(b[0]), "r"(b[1]));
}

__device__ __forceinline__ void cp_async16(uint32_t dst, const void* src, int src_size) {
    asm volatile("cp.async.cg.shared.global [%0], [%1], 16, %2;"
                 :: "r"(dst), "l"(src), "r"(src_size) : "memory");
}
#define CP_COMMIT() asm volatile("cp.async.commit_group;" ::: "memory")
#define CP_WAIT(n)  asm volatile("cp.async.wait_group %0;" :: "n"(n) : "memory")

// smem: [row 0..127][k 0..15] raw fp32, row stride 24 floats, double buffered A|B.
#define GSTRIDE 24
#define GBUF    (128 * GSTRIDE)       // 3072 floats = 12 KB
#define GT_SMEM (4 * GBUF * 4)        // A0|A1|B0|B1 = 48 KB

__device__ __forceinline__ void gemm_issue_stage(
    uint32_t sbase, int buf, const float* A, const float* W,
    int rowBase, int colBase, int N, int Kd, int kb, int tid)
{
    uint32_t aAddr = sbase + (uint32_t)(buf * GBUF * 4);
    uint32_t bAddr = sbase + (uint32_t)((2 * GBUF + buf * GBUF) * 4);
    #pragma unroll
    for (int i = 0; i < 2; i++) {
        int c   = tid + i * 256;
        int row = c >> 2, k4 = c & 3;
        int kg  = kb + k4 * 4;
        int ok  = (kg < Kd) ? 16 : 0;          // Kd % 4 == 0 -> chunk all-or-none
        uint32_t dst = (uint32_t)(row * (GSTRIDE * 4) + k4 * 16);
        cp_async16(aAddr + dst, A + (long)(rowBase + row) * Kd + kg, ok);
        int wr = colBase + row;
        int wc = (wr < N) ? wr : (N - 1);
        cp_async16(bAddr + dst, W + (long)wc * Kd + kg, (wr < N) ? ok : 0);
    }
}

__global__ __launch_bounds__(256) void sgemm_tc(
    const float* __restrict__ Abase, long sA,
    const float* __restrict__ Wbase, long sW,
    float* __restrict__ Cbase, long sC,
    const float* __restrict__ Xbase, long sX,
    int N, int Kd, int epi)
{
    int z = blockIdx.z;
    int Me = g_cnt[z];
    int rowBase = blockIdx.y * 128;
    if (rowBase >= Me) return;
    int colBase = blockIdx.x * 128;

    extern __shared__ __align__(16) float sdyn[];

    const float* A = Abase + (long)z * sA;
    const float* W = Wbase + (long)z * sW;
    float*       C = Cbase + (long)z * sC;
    const float* X = Xbase ? (Xbase + (long)z * sX) : nullptr;

    int tid  = threadIdx.x;
    int wid  = tid >> 5, lane = tid & 31;
    int gid  = lane >> 2, tig = lane & 3;      // mma fragment coords
    int warpM = wid & 3, warpN = wid >> 2;     // 4 x 2 warp grid
    int m0 = warpM * 32;                       // warp tile 32 x 64
    int n0 = warpN * 64;

    uint32_t sbase;
    asm("{ .reg .u64 t; cvta.to.shared.u64 t, %1; cvt.u32.u64 %0, t; }"
        : "=r"(sbase) : "l"((const void*)sdyn));

    float acc[2][8][4];
    #pragma unroll
    for (int i = 0; i < 2; i++)
        #pragma unroll
        for (int j = 0; j < 8; j++)
            #pragma unroll
            for (int q = 0; q < 4; q++) acc[i][j][q] = 0.f;

    int nstages = (Kd + 15) >> 4;
    int kk = 2 * tig;                           // k-pair base for this thread

    gemm_issue_stage(sbase, 0, A, W, rowBase, colBase, N, Kd, 0, tid);
    CP_COMMIT();

    for (int st = 0; st < nstages; st++) {
        if (st + 1 < nstages) {
            gemm_issue_stage(sbase, (st + 1) & 1, A, W, rowBase, colBase, N, Kd,
                             (st + 1) << 4, tid);
            CP_COMMIT();
            CP_WAIT(1);
        } else {
            CP_WAIT(0);
        }
        __syncthreads();

        const float* As = sdyn + (st & 1) * GBUF;
        const float* Bs = sdyn + 2 * GBUF + (st & 1) * GBUF;

        // A: exact fp16 split (hi + lo) in registers
        uint32_t aH[2][4], aL[2][4];
        #pragma unroll
        for (int mf = 0; mf < 2; mf++) {
            int mr0 = (m0 + mf * 16 + gid) * GSTRIDE;
            int mr1 = mr0 + 8 * GSTRIDE;
            split_h2(*(const float2*)(As + mr0 + kk),     aH[mf][0], aL[mf][0]);
            split_h2(*(const float2*)(As + mr1 + kk),     aH[mf][1], aL[mf][1]);
            split_h2(*(const float2*)(As + mr0 + kk + 8), aH[mf][2], aL[mf][2]);
            split_h2(*(const float2*)(As + mr1 + kk + 8), aH[mf][3], aL[mf][3]);
        }
        // B: single fp16 rounding; 2 passes: AH*BH + AL*BH
        #pragma unroll
        for (int nf = 0; nf < 8; nf++) {
            int nr = (n0 + nf * 8 + gid) * GSTRIDE;
            uint32_t bh[2];
            bh[0] = cvt_h2(*(const float2*)(Bs + nr + kk));
            bh[1] = cvt_h2(*(const float2*)(Bs + nr + kk + 8));
            mma_f16(acc[0][nf], aH[0], bh);
            mma_f16(acc[1][nf], aH[1], bh);
            mma_f16(acc[0][nf], aL[0], bh);
            mma_f16(acc[1][nf], aL[1], bh);
        }
        __syncthreads();
    }

    // ---- epilogue ----
    #pragma unroll
    for (int mf = 0; mf < 2; mf++) {
        #pragma unroll
        for (int nf = 0; nf < 8; nf++) {
            #pragma unroll
            for (int q = 0; q < 4; q++) {
                int rr = rowBase + m0 + mf * 16 + gid + (q >> 1) * 8;
                int cc = colBase + n0 + nf * 8 + 2 * tig + (q & 1);
                if (rr < Me && cc < N) {
                    float v = acc[mf][nf][q];
                    long idx = (long)rr * N + cc;
                    if (epi == EPI_SILU)         v = v * (1.f / (1.f + expf(-v)));
                    else if (epi == EPI_SIGMOID) v = 1.f / (1.f + expf(-v));
                    else                         v = v * X[idx];
                    C[idx] = v;
                }
            }
        }
    }
}

// ---------------- K5: combine (res + post, gated sum over experts) -------
__global__ void combine_kernel(const float* __restrict__ stream,
                               float* __restrict__ out)
{
    int t = blockIdx.x;
    int b = t >> 10, tt = t & 1023;
    int tid = threadIdx.x;      // 256
    __shared__ float cres[16];
    __shared__ float pc[KX][4];
    __shared__ float gsh[KX];
    __shared__ int   posh[KX];

    if (tid < KX) {
        gsh[tid]  = g_gate[tid][t];
        posh[tid] = g_pos[tid][t];
    }
    __syncthreads();
    if (tid < 16) {
        float s = 0.f;
        for (int kk = 0; kk < KX; kk++) {
            int p = posh[kk];
            if (p >= 0) s += gsh[kk] * g_Hres[kk][p][tid];
        }
        cres[tid] = s;
    } else if (tid >= 32 && tid < 32 + KX * 4) {
        int idx = tid - 32; int kk = idx >> 2, i = idx & 3;
        int p = posh[kk];
        pc[kk][i] = (p >= 0) ? gsh[kk] * g_Hpost[kk][p][i] : 0.f;
    }
    __syncthreads();

    for (int d = tid; d < D_; d += 256) {
        float sj[4];
        #pragma unroll
        for (int j = 0; j < 4; j++)
            sj[j] = stream[(((long)(b * N_ + j)) * T_ + tt) * D_ + d];
        float r[4];
        #pragma unroll
        for (int i = 0; i < 4; i++)
            r[i] = cres[i * 4 + 0] * sj[0] + cres[i * 4 + 1] * sj[1]
                 + cres[i * 4 + 2] * sj[2] + cres[i * 4 + 3] * sj[3];
        for (int kk = 0; kk < KX; kk++) {
            int p = posh[kk];
            if (p >= 0) {
                float oe = g_oute[kk][p][d];
                #pragma unroll
                for (int i = 0; i < 4; i++) r[i] += pc[kk][i] * oe;
            }
        }
        #pragma unroll
        for (int i = 0; i < 4; i++)
            out[(((long)(b * N_ + i)) * T_ + tt) * D_ + d] = r[i];
    }
}

// ---------------- launch ----------------
extern "C" void kernel_launch(void* const* d_in, const int* in_sizes, int n_in,
                              void* d_out, int out_size)
{
    const float* stream    = (const float*)d_in[0];
    const float* norm_w    = (const float*)d_in[1];
    const float* phi_pre   = (const float*)d_in[2];
    const float* phi_post  = (const float*)d_in[3];
    const float* phi_res   = (const float*)d_in[4];
    const float* b_pre     = (const float*)d_in[5];
    const float* b_post    = (const float*)d_in[6];
    const float* b_res     = (const float*)d_in[7];
    const float* alpha_pre = (const float*)d_in[8];
    const float* alpha_post= (const float*)d_in[9];
    const float* alpha_res = (const float*)d_in[10];
    const float* snw       = (const float*)d_in[11];
    const float* wd        = (const float*)d_in[12];
    const float* wu        = (const float*)d_in[13];
    const float* wg        = (const float*)d_in[14];
    const float* wup       = (const float*)d_in[15];
    const float* wdn       = (const float*)d_in[16];
    const float* rw        = (const float*)d_in[17];
    float* out = (float*)d_out;

    float *p_h, *p_s1, *p_g, *p_t1, *p_t2, *p_oe;
    cudaGetSymbolAddress((void**)&p_h,  g_h);
    cudaGetSymbolAddress((void**)&p_s1, g_s1);
    cudaGetSymbolAddress((void**)&p_g,  g_gsig);
    cudaGetSymbolAddress((void**)&p_t1, g_t1);
    cudaGetSymbolAddress((void**)&p_t2, g_t2);
    cudaGetSymbolAddress((void**)&p_oe, g_oute);

    cudaFuncSetAttribute(sgemm_tc, cudaFuncAttributeMaxDynamicSharedMemorySize, GT_SMEM);

    zero_cnt_kernel<<<1, 32>>>();
    routing_kernel<<<MTOK, 128>>>(stream, rw, out);
    xn_kernel<<<MTOK, 256>>>(stream);
    mhc_part<<<dim3(16, KX, KSPLIT), 256>>>(norm_w, phi_pre, phi_post, phi_res);
    mhc_epi<<<dim3(16, KX), 128>>>(b_pre, b_post, b_res,
                                   alpha_pre, alpha_post, alpha_res);
    he_kernel<<<dim3(KX, MTOK), 128>>>(stream, snw);

    long sHD = (long)MTOK * D_;
    long sHF = (long)MTOK * DFFN;

    // s1 = silu(h @ wd^T)
    sgemm_tc<<<dim3(4, 16, KX), 256, GT_SMEM>>>(p_h, sHD, wd + (long)D_ * D_,
                                                (long)D_ * D_, p_s1, sHD,
                                                nullptr, 0, D_, D_, EPI_SILU);
    // g = sigmoid(s1 @ wu^T)
    sgemm_tc<<<dim3(4, 16, KX), 256, GT_SMEM>>>(p_s1, sHD, wu + (long)D_ * D_,
                                                (long)D_ * D_, p_g, sHD,
                                                nullptr, 0, D_, D_, EPI_SIGMOID);
    // t1 = silu(h @ gate^T)
    sgemm_tc<<<dim3(7, 16, KX), 256, GT_SMEM>>>(p_h, sHD, wg + (long)DFFN * D_,
                                                (long)DFFN * D_, p_t1, sHF,
                                                nullptr, 0, DFFN, D_, EPI_SILU);
    // t2 = (h @ up^T) * t1
    sgemm_tc<<<dim3(7, 16, KX), 256, GT_SMEM>>>(p_h, sHD, wup + (long)DFFN * D_,
                                                (long)DFFN * D_, p_t2, sHF,
                                                p_t1, sHF, DFFN, D_, EPI_MUL);
    // out_e = (t2 @ down^T) * g
    sgemm_tc<<<dim3(4, 16, KX), 256, GT_SMEM>>>(p_t2, sHF, wdn + (long)D_ * DFFN,
                                                (long)D_ * DFFN, p_oe, sHD,
                                                p_g, sHD, D_, DFFN, EPI_MUL);

    combine_kernel<<<MTOK, 256>>>(stream, out);
}

// round 16
// speedup vs baseline: 1.9846x; 1.0680x over previous
#include <cuda_runtime.h>
#include <cuda_fp16.h>
#include <math.h>
#include <stdint.h>

#define B_   2
#define N_   4
#define T_   1024
#define D_   512
#define E_   16
#define KX   15          // computed experts (1..15)
#define DFFN 828
#define ND   2048        // N_*D_
#define MTOK 2048        // B_*T_
#define KSPLIT 32        // split-K factor for MHC projection

// ---------------- scratch (device globals; no allocation) ----------------
__device__ float g_xn[MTOK * ND];
__device__ int   g_cnt[KX];
__device__ int   g_idx[KX][MTOK];
__device__ int   g_pos[KX][MTOK];
__device__ float g_rs[(long)KX * 16 * 24 * KSPLIT * 128];
__device__ float g_Hpre[KX][MTOK][4];
__device__ float g_Hpost[KX][MTOK][4];
__device__ float g_Hres[KX][MTOK][16];
__device__ float g_gate[KX][MTOK];
__device__ float g_h[KX][MTOK][D_];
__device__ float g_s1[KX][MTOK][D_];
__device__ float g_gsig[KX][MTOK][D_];
__device__ float g_t1[KX][MTOK][DFFN];
__device__ float g_t2[KX][MTOK][DFFN];
__device__ float g_oute[KX][MTOK][D_];

__device__ __forceinline__ float sigmoidf_(float x) { return 1.f / (1.f + expf(-x)); }

__device__ __forceinline__ float block_reduce_sum(float v, float* sbuf) {
    int tid = threadIdx.x;
    #pragma unroll
    for (int o = 16; o > 0; o >>= 1) v += __shfl_down_sync(0xffffffffu, v, o);
    if ((tid & 31) == 0) sbuf[tid >> 5] = v;
    __syncthreads();
    int nw = blockDim.x >> 5;
    float r = (tid < nw) ? sbuf[tid] : 0.f;
    if (tid < 32) {
        #pragma unroll
        for (int o = 16; o > 0; o >>= 1) r += __shfl_down_sync(0xffffffffu, r, o);
        if (tid == 0) sbuf[0] = r;
    }
    __syncthreads();
    return sbuf[0];
}

// ---------------- K-1: zero per-expert counters ---------------------------
__global__ void zero_cnt_kernel() {
    if (threadIdx.x < KX) g_cnt[threadIdx.x] = 0;
}

// ---------------- K0: routing + compaction lists --------------------------
__global__ void routing_kernel(const float* __restrict__ stream,
                               const float* __restrict__ router_w,
                               float* __restrict__ out)
{
    int t = blockIdx.x;
    int b = t >> 10, tt = t & 1023;
    int tid = threadIdx.x;           // 128
    __shared__ float sred[E_][128];

    float acc[E_];
    #pragma unroll
    for (int e = 0; e < E_; e++) acc[e] = 0.f;

    for (int d = tid; d < D_; d += 128) {
        float ri = 0.f;
        #pragma unroll
        for (int n = 0; n < N_; n++)
            ri += stream[(((long)(b * N_ + n)) * T_ + tt) * D_ + d];
        ri *= 0.25f;
        #pragma unroll
        for (int e = 0; e < E_; e++) acc[e] += ri * router_w[e * D_ + d];
    }
    #pragma unroll
    for (int e = 0; e < E_; e++) sred[e][tid] = acc[e];
    __syncthreads();
    for (int s = 64; s > 0; s >>= 1) {
        if (tid < s) {
            #pragma unroll
            for (int e = 0; e < E_; e++) sred[e][tid] += sred[e][tid + s];
        }
        __syncthreads();
    }

    if (tid == 0) {
        float probs[E_];
        float mx = -1e30f;
        for (int e = 0; e < E_; e++) mx = fmaxf(mx, sred[e][0]);
        float ssum = 0.f;
        for (int e = 0; e < E_; e++) { probs[e] = expf(sred[e][0] - mx); ssum += probs[e]; }
        float inv = 1.f / ssum;
        for (int e = 0; e < E_; e++) probs[e] *= inv;

        int order[E_];
        for (int e = 0; e < E_; e++) order[e] = e;
        for (int i = 1; i < E_; i++) {
            int oi = order[i]; float p = probs[oi]; int j = i - 1;
            while (j >= 0 && probs[order[j]] < p) { order[j + 1] = order[j]; j--; }
            order[j + 1] = oi;
        }
        float gate[E_];
        for (int e = 0; e < E_; e++) gate[e] = 0.f;
        float cum = 0.f;
        for (int i = 0; i < E_; i++) {
            float p = probs[order[i]];
            bool m = (i == 0) || ((cum < 0.8f) && (i < 4));
            if (m) gate[order[i]] = p;
            cum += p;
        }
        float lp = 0.f;
        for (int e = 0; e < E_; e++)
            if (gate[e] > 0.f) lp += fmaxf(logf(probs[e]), -10.f);

        float* out_gate = out + (long)B_ * N_ * T_ * D_;
        float* out_lp   = out_gate + (long)B_ * T_ * E_;
        for (int e = 0; e < E_; e++) out_gate[(long)t * E_ + e] = gate[e];
        out_lp[t] = lp;
        for (int k = 0; k < KX; k++) {
            float gk = gate[k + 1];
            g_gate[k][t] = gk;
            if (gk > 0.f) {
                int p = atomicAdd(&g_cnt[k], 1);
                g_idx[k][p] = t;
                g_pos[k][t] = p;
            } else {
                g_pos[k][t] = -1;
            }
        }
    }
}

// ---------------- K1: xn = RMSNorm over nd of transposed stream ----------
__global__ void xn_kernel(const float* __restrict__ stream)
{
    int t = blockIdx.x;
    int b = t >> 10, tt = t & 1023;
    int tid = threadIdx.x;           // 256
    __shared__ float sbuf[32];
    float v[8]; float ss = 0.f;
    #pragma unroll
    for (int i = 0; i < 8; i++) {
        int j = tid + i * 256;
        int n = j >> 9, d = j & 511;
        float x = stream[(((long)(b * N_ + n)) * T_ + tt) * D_ + d];
        v[i] = x; ss += x * x;
    }
    float tot = block_reduce_sum(ss, sbuf);
    float rms = rsqrtf(tot * (1.f / ND) + 1e-8f);
    #pragma unroll
    for (int i = 0; i < 8; i++)
        g_xn[(long)t * ND + tid + i * 256] = v[i] * rms;
}

// ---------------- K2a: MHC projection partials (split-K) -----------------
__global__ __launch_bounds__(256, 4) void mhc_part(
    const float* __restrict__ norm_w,
    const float* __restrict__ phi_pre, const float* __restrict__ phi_post,
    const float* __restrict__ phi_res)
{
    int tile = blockIdx.x;
    int k = blockIdx.y; int e = k + 1;
    int ks = blockIdx.z;
    int t0 = tile * 128;
    int cnt = g_cnt[k];
    if (t0 >= cnt) return;
    int tid = threadIdx.x;

    __shared__ int   tok[128];
    __shared__ float xs[32][129];
    __shared__ float ws[32][25];

    if (tid < 128) {
        int s = t0 + tid;
        tok[tid] = (s < cnt) ? g_idx[k][s] : g_idx[k][0];
    }
    __syncthreads();

    int r = tid & 63;
    int q = tid >> 6;

    float acc[2][6];
    #pragma unroll
    for (int a = 0; a < 2; a++)
        #pragma unroll
        for (int m = 0; m < 6; m++) acc[a][m] = 0.f;

    const int kbeg = ks * (ND / KSPLIT);
    const int kend = kbeg + (ND / KSPLIT);
    for (int kb = kbeg; kb < kend; kb += 32) {
        #pragma unroll
        for (int i = 0; i < 16; i++) {
            int lin = tid + i * 256;
            int trow = lin >> 5, tcol = lin & 31;
            xs[tcol][trow] = g_xn[(long)tok[trow] * ND + kb + tcol];
        }
        #pragma unroll
        for (int i = 0; i < 3; i++) {
            int lin = tid + i * 256;
            int jrow = lin >> 5, kcol = lin & 31;
            int gk = kb + kcol;
            const float* wr;
            if (jrow < 4)      wr = phi_pre  + (long)(e * 4  + jrow)       * ND;
            else if (jrow < 8) wr = phi_post + (long)(e * 4  + (jrow - 4)) * ND;
            else               wr = phi_res  + (long)(e * 16 + (jrow - 8)) * ND;
            ws[kcol][jrow] = wr[gk] * norm_w[(long)e * ND + gk];
        }
        __syncthreads();
        #pragma unroll
        for (int kk = 0; kk < 32; kk++) {
            float x0 = xs[kk][r], x1 = xs[kk][r + 64];
            #pragma unroll
            for (int m = 0; m < 6; m++) {
                float w = ws[kk][q + m * 4];
                acc[0][m] += x0 * w;
                acc[1][m] += x1 * w;
            }
        }
        __syncthreads();
    }

    long base = ((long)(k * 16 + tile)) * 24;
    #pragma unroll
    for (int m = 0; m < 6; m++) {
        int j = q + m * 4;
        long o = ((base + j) * KSPLIT + ks) * 128;
        g_rs[o + r]      = acc[0][m];
        g_rs[o + r + 64] = acc[1][m];
    }
}

// ---------------- K2b: sum partials + sigmoid/sinkhorn epilogue ----------
__global__ void mhc_epi(
    const float* __restrict__ b_pre, const float* __restrict__ b_post,
    const float* __restrict__ b_res,
    const float* __restrict__ alpha_pre, const float* __restrict__ alpha_post,
    const float* __restrict__ alpha_res)
{
    int tile = blockIdx.x;
    int k = blockIdx.y; int e = k + 1;
    int cnt = g_cnt[k];
    int slot = tile * 128 + threadIdx.x;
    if (slot >= cnt) return;

    float rsv[24];
    long base = ((long)(k * 16 + tile)) * 24;
    #pragma unroll
    for (int j = 0; j < 24; j++) {
        long o = (base + j) * KSPLIT * 128 + threadIdx.x;
        float s = 0.f;
        #pragma unroll
        for (int ks = 0; ks < KSPLIT; ks++) s += g_rs[o + (long)ks * 128];
        rsv[j] = s;
    }

    float ap  = alpha_pre[e];
    float apo = alpha_post[e];
    float ar  = alpha_res[e];
    #pragma unroll
    for (int n = 0; n < 4; n++) {
        g_Hpre[k][slot][n]  = sigmoidf_(ap  * rsv[n]     + b_pre[e * 4 + n]);
        g_Hpost[k][slot][n] = 2.f * sigmoidf_(apo * rsv[4 + n] + b_post[e * 4 + n]);
    }
    float m[4][4];
    #pragma unroll
    for (int i = 0; i < 4; i++)
        #pragma unroll
        for (int j = 0; j < 4; j++)
            m[i][j] = expf(ar * rsv[8 + i * 4 + j] + b_res[e * 16 + i * 4 + j]);
    #pragma unroll
    for (int it = 0; it < 6; it++) {
        #pragma unroll
        for (int i = 0; i < 4; i++) {
            float s = m[i][0] + m[i][1] + m[i][2] + m[i][3];
            float iv = 1.f / s;
            m[i][0] *= iv; m[i][1] *= iv; m[i][2] *= iv; m[i][3] *= iv;
        }
        #pragma unroll
        for (int j = 0; j < 4; j++) {
            float s = m[0][j] + m[1][j] + m[2][j] + m[3][j];
            float iv = 1.f / s;
            m[0][j] *= iv; m[1][j] *= iv; m[2][j] *= iv; m[3][j] *= iv;
        }
    }
    #pragma unroll
    for (int i = 0; i < 4; i++)
        #pragma unroll
        for (int j = 0; j < 4; j++)
            g_Hres[k][slot][i * 4 + j] = m[i][j];
}

// ---------------- K3: h = RMSNorm(H_pre @ stream) * swiglu_norm_w --------
__global__ void he_kernel(const float* __restrict__ stream,
                          const float* __restrict__ snw)
{
    int k = blockIdx.x;
    int slot = blockIdx.y;
    if (slot >= g_cnt[k]) return;
    int t = g_idx[k][slot];
    int b = t >> 10, tt = t & 1023;
    int tid = threadIdx.x;
    __shared__ float sbuf[32];

    float hp[4];
    #pragma unroll
    for (int n = 0; n < 4; n++) hp[n] = g_Hpre[k][slot][n];

    float v[4]; float ss = 0.f;
    #pragma unroll
    for (int i = 0; i < 4; i++) {
        int d = tid + i * 128;
        float s = 0.f;
        #pragma unroll
        for (int n = 0; n < 4; n++)
            s += hp[n] * stream[(((long)(b * N_ + n)) * T_ + tt) * D_ + d];
        v[i] = s; ss += s * s;
    }
    float tot = block_reduce_sum(ss, sbuf);
    float rms = rsqrtf(tot * (1.f / D_) + 1e-8f);
    int e = k + 1;
    #pragma unroll
    for (int i = 0; i < 4; i++) {
        int d = tid + i * 128;
        g_h[k][slot][d] = v[i] * rms * snw[e * D_ + d];
    }
}

// ---------------- single-pass FP16 mma.sync GEMM, cp.async pipeline ------
// C[M,N] = epi(A[M,Kd] @ W[N,Kd]^T): both operands rounded once to fp16.
// 16 HMMA per stage per warp.
#define EPI_SILU    0
#define EPI_SIGMOID 1
#define EPI_MUL     2

__device__ __forceinline__ uint32_t cvt_h2(float2 v) {
    __half2 h = __float22half2_rn(v);
    return *(uint32_t*)&h;
}

__device__ __forceinline__ void mma_f16(float* c, const uint32_t* a, const uint32_t* b) {
    asm volatile(
        "mma.sync.aligned.m16n8k16.row.col.f32.f16.f16.f32 "
        "{%0,%1,%2,%3}, {%4,%5,%6,%7}, {%8,%9}, {%0,%1,%2,%3};"
        : "+f"(c[0]), "+f"(c[1]), "+f"(c[2]), "+f"(c[3])
        : "r"(a[0]), "r"(a[1]), "r"(a[2]), "r"(a[3]), "r"(b[0]), "r"(b[1]));
}

__device__ __forceinline__ void cp_async16(uint32_t dst, const void* src, int src_size) {
    asm volatile("cp.async.cg.shared.global [%0], [%1], 16, %2;"
                 :: "r"(dst), "l"(src), "r"(src_size) : "memory");
}
#define CP_COMMIT() asm volatile("cp.async.commit_group;" ::: "memory")
#define CP_WAIT(n)  asm volatile("cp.async.wait_group %0;" :: "n"(n) : "memory")

// smem: [row 0..127][k 0..15] raw fp32, row stride 24 floats, double buffered A|B.
#define GSTRIDE 24
#define GBUF    (128 * GSTRIDE)       // 3072 floats = 12 KB
#define GT_SMEM (4 * GBUF * 4)        // A0|A1|B0|B1 = 48 KB

__device__ __forceinline__ void gemm_issue_stage(
    uint32_t sbase, int buf, const float* A, const float* W,
    int rowBase, int colBase, int N, int Kd, int kb, int tid)
{
    uint32_t aAddr = sbase + (uint32_t)(buf * GBUF * 4);
    uint32_t bAddr = sbase + (uint32_t)((2 * GBUF + buf * GBUF) * 4);
    #pragma unroll
    for (int i = 0; i < 2; i++) {
        int c   = tid + i * 256;
        int row = c >> 2, k4 = c & 3;
        int kg  = kb + k4 * 4;
        int ok  = (kg < Kd) ? 16 : 0;          // Kd % 4 == 0 -> chunk all-or-none
        uint32_t dst = (uint32_t)(row * (GSTRIDE * 4) + k4 * 16);
        cp_async16(aAddr + dst, A + (long)(rowBase + row) * Kd + kg, ok);
        int wr = colBase + row;
        int wc = (wr < N) ? wr : (N - 1);
        cp_async16(bAddr + dst, W + (long)wc * Kd + kg, (wr < N) ? ok : 0);
    }
}

__global__ __launch_bounds__(256) void sgemm_tc(
    const float* __restrict__ Abase, long sA,
    const float* __restrict__ Wbase, long sW,
    float* __restrict__ Cbase, long sC,
    const float* __restrict__ Xbase, long sX,
    int N, int Kd, int epi)
{
    int z = blockIdx.z;
    int Me = g_cnt[z];
    int rowBase = blockIdx.y * 128;
    if (rowBase >= Me) return;
    int colBase = blockIdx.x * 128;

    extern __shared__ __align__(16) float sdyn[];

    const float* A = Abase + (long)z * sA;
    const float* W = Wbase + (long)z * sW;
    float*       C = Cbase + (long)z * sC;
    const float* X = Xbase ? (Xbase + (long)z * sX) : nullptr;

    int tid  = threadIdx.x;
    int wid  = tid >> 5, lane = tid & 31;
    int gid  = lane >> 2, tig = lane & 3;      // mma fragment coords
    int warpM = wid & 3, warpN = wid >> 2;     // 4 x 2 warp grid
    int m0 = warpM * 32;                       // warp tile 32 x 64
    int n0 = warpN * 64;

    uint32_t sbase;
    asm("{ .reg .u64 t; cvta.to.shared.u64 t, %1; cvt.u32.u64 %0, t; }"
        : "=r"(sbase) : "l"((const void*)sdyn));

    float acc[2][8][4];
    #pragma unroll
    for (int i = 0; i < 2; i++)
        #pragma unroll
        for (int j = 0; j < 8; j++)
            #pragma unroll
            for (int q = 0; q < 4; q++) acc[i][j][q] = 0.f;

    int nstages = (Kd + 15) >> 4;
    int kk = 2 * tig;                           // k-pair base for this thread

    gemm_issue_stage(sbase, 0, A, W, rowBase, colBase, N, Kd, 0, tid);
    CP_COMMIT();

    for (int st = 0; st < nstages; st++) {
        if (st + 1 < nstages) {
            gemm_issue_stage(sbase, (st + 1) & 1, A, W, rowBase, colBase, N, Kd,
                             (st + 1) << 4, tid);
            CP_COMMIT();
            CP_WAIT(1);
        } else {
            CP_WAIT(0);
        }
        __syncthreads();

        const float* As = sdyn + (st & 1) * GBUF;
        const float* Bs = sdyn + 2 * GBUF + (st & 1) * GBUF;

        // A: rounded once to fp16 in registers
        uint32_t aH[2][4];
        #pragma unroll
        for (int mf = 0; mf < 2; mf++) {
            int mr0 = (m0 + mf * 16 + gid) * GSTRIDE;
            int mr1 = mr0 + 8 * GSTRIDE;
            aH[mf][0] = cvt_h2(*(const float2*)(As + mr0 + kk));
            aH[mf][1] = cvt_h2(*(const float2*)(As + mr1 + kk));
            aH[mf][2] = cvt_h2(*(const float2*)(As + mr0 + kk + 8));
            aH[mf][3] = cvt_h2(*(const float2*)(As + mr1 + kk + 8));
        }
        // B: rounded once; single pass AH*BH
        #pragma unroll
        for (int nf = 0; nf < 8; nf++) {
            int nr = (n0 + nf * 8 + gid) * GSTRIDE;
            uint32_t bh[2];
            bh[0] = cvt_h2(*(const float2*)(Bs + nr + kk));
            bh[1] = cvt_h2(*(const float2*)(Bs + nr + kk + 8));
            mma_f16(acc[0][nf], aH[0], bh);
            mma_f16(acc[1][nf], aH[1], bh);
        }
        __syncthreads();
    }

    // ---- epilogue ----
    #pragma unroll
    for (int mf = 0; mf < 2; mf++) {
        #pragma unroll
        for (int nf = 0; nf < 8; nf++) {
            #pragma unroll
            for (int q = 0; q < 4; q++) {
                int rr = rowBase + m0 + mf * 16 + gid + (q >> 1) * 8;
                int cc = colBase + n0 + nf * 8 + 2 * tig + (q & 1);
                if (rr < Me && cc < N) {
                    float v = acc[mf][nf][q];
                    long idx = (long)rr * N + cc;
                    if (epi == EPI_SILU)         v = v * (1.f / (1.f + expf(-v)));
                    else if (epi == EPI_SIGMOID) v = 1.f / (1.f + expf(-v));
                    else                         v = v * X[idx];
                    C[idx] = v;
                }
            }
        }
    }
}

// ---------------- K5: combine (res + post, gated sum over experts) -------
__global__ void combine_kernel(const float* __restrict__ stream,
                               float* __restrict__ out)
{
    int t = blockIdx.x;
    int b = t >> 10, tt = t & 1023;
    int tid = threadIdx.x;      // 256
    __shared__ float cres[16];
    __shared__ float pc[KX][4];
    __shared__ float gsh[KX];
    __shared__ int   posh[KX];

    if (tid < KX) {
        gsh[tid]  = g_gate[tid][t];
        posh[tid] = g_pos[tid][t];
    }
    __syncthreads();
    if (tid < 16) {
        float s = 0.f;
        for (int kk = 0; kk < KX; kk++) {
            int p = posh[kk];
            if (p >= 0) s += gsh[kk] * g_Hres[kk][p][tid];
        }
        cres[tid] = s;
    } else if (tid >= 32 && tid < 32 + KX * 4) {
        int idx = tid - 32; int kk = idx >> 2, i = idx & 3;
        int p = posh[kk];
        pc[kk][i] = (p >= 0) ? gsh[kk] * g_Hpost[kk][p][i] : 0.f;
    }
    __syncthreads();

    for (int d = tid; d < D_; d += 256) {
        float sj[4];
        #pragma unroll
        for (int j = 0; j < 4; j++)
            sj[j] = stream[(((long)(b * N_ + j)) * T_ + tt) * D_ + d];
        float r[4];
        #pragma unroll
        for (int i = 0; i < 4; i++)
            r[i] = cres[i * 4 + 0] * sj[0] + cres[i * 4 + 1] * sj[1]
                 + cres[i * 4 + 2] * sj[2] + cres[i * 4 + 3] * sj[3];
        for (int kk = 0; kk < KX; kk++) {
            int p = posh[kk];
            if (p >= 0) {
                float oe = g_oute[kk][p][d];
                #pragma unroll
                for (int i = 0; i < 4; i++) r[i] += pc[kk][i] * oe;
            }
        }
        #pragma unroll
        for (int i = 0; i < 4; i++)
            out[(((long)(b * N_ + i)) * T_ + tt) * D_ + d] = r[i];
    }
}

// ---------------- launch ----------------
extern "C" void kernel_launch(void* const* d_in, const int* in_sizes, int n_in,
                              void* d_out, int out_size)
{
    const float* stream    = (const float*)d_in[0];
    const float* norm_w    = (const float*)d_in[1];
    const float* phi_pre   = (const float*)d_in[2];
    const float* phi_post  = (const float*)d_in[3];
    const float* phi_res   = (const float*)d_in[4];
    const float* b_pre     = (const float*)d_in[5];
    const float* b_post    = (const float*)d_in[6];
    const float* b_res     = (const float*)d_in[7];
    const float* alpha_pre = (const float*)d_in[8];
    const float* alpha_post= (const float*)d_in[9];
    const float* alpha_res = (const float*)d_in[10];
    const float* snw       = (const float*)d_in[11];
    const float* wd        = (const float*)d_in[12];
    const float* wu        = (const float*)d_in[13];
    const float* wg        = (const float*)d_in[14];
    const float* wup       = (const float*)d_in[15];
    const float* wdn       = (const float*)d_in[16];
    const float* rw        = (const float*)d_in[17];
    float* out = (float*)d_out;

    float *p_h, *p_s1, *p_g, *p_t1, *p_t2, *p_oe;
    cudaGetSymbolAddress((void**)&p_h,  g_h);
    cudaGetSymbolAddress((void**)&p_s1, g_s1);
    cudaGetSymbolAddress((void**)&p_g,  g_gsig);
    cudaGetSymbolAddress((void**)&p_t1, g_t1);
    cudaGetSymbolAddress((void**)&p_t2, g_t2);
    cudaGetSymbolAddress((void**)&p_oe, g_oute);

    cudaFuncSetAttribute(sgemm_tc, cudaFuncAttributeMaxDynamicSharedMemorySize, GT_SMEM);

    zero_cnt_kernel<<<1, 32>>>();
    routing_kernel<<<MTOK, 128>>>(stream, rw, out);
    xn_kernel<<<MTOK, 256>>>(stream);
    mhc_part<<<dim3(16, KX, KSPLIT), 256>>>(norm_w, phi_pre, phi_post, phi_res);
    mhc_epi<<<dim3(16, KX), 128>>>(b_pre, b_post, b_res,
                                   alpha_pre, alpha_post, alpha_res);
    he_kernel<<<dim3(KX, MTOK), 128>>>(stream, snw);

    long sHD = (long)MTOK * D_;
    long sHF = (long)MTOK * DFFN;

    // s1 = silu(h @ wd^T)
    sgemm_tc<<<dim3(4, 16, KX), 256, GT_SMEM>>>(p_h, sHD, wd + (long)D_ * D_,
                                                (long)D_ * D_, p_s1, sHD,
                                                nullptr, 0, D_, D_, EPI_SILU);
    // g = sigmoid(s1 @ wu^T)
    sgemm_tc<<<dim3(4, 16, KX), 256, GT_SMEM>>>(p_s1, sHD, wu + (long)D_ * D_,
                                                (long)D_ * D_, p_g, sHD,
                                                nullptr, 0, D_, D_, EPI_SIGMOID);
    // t1 = silu(h @ gate^T)
    sgemm_tc<<<dim3(7, 16, KX), 256, GT_SMEM>>>(p_h, sHD, wg + (long)DFFN * D_,
                                                (long)DFFN * D_, p_t1, sHF,
                                                nullptr, 0, DFFN, D_, EPI_SILU);
    // t2 = (h @ up^T) * t1
    sgemm_tc<<<dim3(7, 16, KX), 256, GT_SMEM>>>(p_h, sHD, wup + (long)DFFN * D_,
                                                (long)DFFN * D_, p_t2, sHF,
                                                p_t1, sHF, DFFN, D_, EPI_MUL);
    // out_e = (t2 @ down^T) * g
    sgemm_tc<<<dim3(4, 16, KX), 256, GT_SMEM>>>(p_t2, sHF, wdn + (long)D_ * DFFN,
                                                (long)D_ * DFFN, p_oe, sHD,
                                                p_g, sHD, D_, DFFN, EPI_MUL);

    combine_kernel<<<MTOK, 256>>>(stream, out);
}